// round 2
// baseline (speedup 1.0000x reference)
#include <cuda_runtime.h>
#include <math.h>

// ---------------- problem constants ----------------
#define BATCH 256
#define EDIM  512
#define VDIM  27000
#define LSTEPS 16
#define CMAX  200
#define KZ    1536   // z = [emb(512) | attended(512) | h(512)]
#define GDIM  2048   // 4*E

// ---------------- persistent device scratch ----------------
__device__ float g_att[32768 * EDIM];      // encoded_paths @ attn_W + attn_b
__device__ float g_Wg[KZ * GDIM];          // fused [W_ih | W_hh] transposed to [K, N]
__device__ float g_bg[GDIM];               // b_ih + b_hh
__device__ float g_h[BATCH * EDIM];
__device__ float g_c[BATCH * EDIM];
__device__ float g_z[BATCH * KZ];
__device__ float g_gates[BATCH * GDIM];
__device__ int   g_off[BATCH + 1];
__device__ int   g_cur[BATCH];

// ---------------- init: offsets prefix sum + initial tokens ----------------
__global__ void init_meta_kernel(const int* __restrict__ counts,
                                 const int* __restrict__ target_labels) {
    __shared__ int s[BATCH];
    int t = threadIdx.x;
    s[t] = counts[t];
    __syncthreads();
    for (int d = 1; d < BATCH; d <<= 1) {
        int v = (t >= d) ? s[t - d] : 0;
        __syncthreads();
        s[t] += v;
        __syncthreads();
    }
    g_off[t] = s[t] - counts[t];
    if (t == 0) g_off[BATCH] = s[BATCH - 1];
    g_cur[t] = target_labels[t];   // row 0 of [L, B]
}

// ---------------- build fused gate weights ----------------
__global__ void build_wg_kernel(const float* __restrict__ W_ih,
                                const float* __restrict__ W_hh,
                                const float* __restrict__ b_ih,
                                const float* __restrict__ b_hh) {
    int i = blockIdx.x * blockDim.x + threadIdx.x;
    if (i < KZ * GDIM) {
        int k = i / GDIM, n = i % GDIM;
        g_Wg[i] = (k < 1024) ? W_ih[(size_t)n * 1024 + k]
                             : W_hh[(size_t)n * 512 + (k - 1024)];
    }
    if (i < GDIM) g_bg[i] = b_ih[i] + b_hh[i];
}

// ---------------- init h0 = c0 = mean of contexts ----------------
__global__ void init_h_kernel(const float* __restrict__ enc,
                              const int* __restrict__ counts) {
    int b = blockIdx.x, t = threadIdx.x;
    int cnt = counts[b], off = g_off[b];
    float2 acc = make_float2(0.f, 0.f);
    for (int c = 0; c < cnt; c++) {
        float2 v = *(const float2*)(enc + (size_t)(off + c) * EDIM + 2 * t);
        acc.x += v.x; acc.y += v.y;
    }
    float inv = 1.f / (float)cnt;
    float h0 = acc.x * inv, h1 = acc.y * inv;
    g_h[b * EDIM + 2 * t]     = h0;  g_c[b * EDIM + 2 * t]     = h0;
    g_h[b * EDIM + 2 * t + 1] = h1;  g_c[b * EDIM + 2 * t + 1] = h1;
}

// ---------------- zero the step-0 output slab ----------------
__global__ void zero_kernel(float4* __restrict__ p, int n4) {
    for (int i = blockIdx.x * blockDim.x + threadIdx.x; i < n4; i += gridDim.x * blockDim.x)
        p[i] = make_float4(0.f, 0.f, 0.f, 0.f);
}

// ---------------- SGEMM body: C[M,N] = A[M,K] @ B[K,N] + bias ----------------
template<int BM, int BN, int BK, int TM, int TN>
__device__ __forceinline__ void sgemm_body(const float* __restrict__ A,
                                           const float* __restrict__ B,
                                           const float* __restrict__ bias,
                                           float* __restrict__ C,
                                           int M, int N, int K) {
    constexpr int NT = (BM / TM) * (BN / TN);   // 256
    __shared__ float As[BK][BM];
    __shared__ float Bs[BK][BN];
    int tid = threadIdx.x;
    int bn0 = blockIdx.x * BN;
    int bm0 = blockIdx.y * BM;
    int tx = tid % (BN / TN);
    int ty = tid / (BN / TN);

    float acc[TM][TN];
#pragma unroll
    for (int i = 0; i < TM; i++)
#pragma unroll
        for (int j = 0; j < TN; j++) acc[i][j] = 0.f;

    for (int k0 = 0; k0 < K; k0 += BK) {
        // load A tile (transposed into As[k][m])
#pragma unroll
        for (int i = tid * 4; i < BM * BK; i += NT * 4) {
            int r = i / BK, kk = i % BK;
            int m = bm0 + r;
            float4 v = make_float4(0.f, 0.f, 0.f, 0.f);
            if (m < M) v = *(const float4*)(A + (size_t)m * K + k0 + kk);
            As[kk + 0][r] = v.x; As[kk + 1][r] = v.y;
            As[kk + 2][r] = v.z; As[kk + 3][r] = v.w;
        }
        // load B tile
#pragma unroll
        for (int i = tid * 4; i < BK * BN; i += NT * 4) {
            int r = i / BN, cc = i % BN;
            int n = bn0 + cc;
            float4 v = make_float4(0.f, 0.f, 0.f, 0.f);
            const float* src = B + (size_t)(k0 + r) * N + n;
            if (n + 3 < N) {
                v = *(const float4*)src;
            } else {
                if (n     < N) v.x = src[0];
                if (n + 1 < N) v.y = src[1];
                if (n + 2 < N) v.z = src[2];
                if (n + 3 < N) v.w = src[3];
            }
            *(float4*)&Bs[r][cc] = v;
        }
        __syncthreads();
#pragma unroll
        for (int k = 0; k < BK; k++) {
            float ra[TM], rb[TN];
#pragma unroll
            for (int i = 0; i < TM; i += 4)
                *(float4*)&ra[i] = *(const float4*)&As[k][ty * TM + i];
#pragma unroll
            for (int j = 0; j < TN; j += 4)
                *(float4*)&rb[j] = *(const float4*)&Bs[k][tx * TN + j];
#pragma unroll
            for (int i = 0; i < TM; i++)
#pragma unroll
                for (int j = 0; j < TN; j++)
                    acc[i][j] += ra[i] * rb[j];
        }
        __syncthreads();
    }
#pragma unroll
    for (int i = 0; i < TM; i++) {
        int m = bm0 + ty * TM + i;
        if (m >= M) continue;
#pragma unroll
        for (int j = 0; j < TN; j++) {
            int n = bn0 + tx * TN + j;
            if (n < N) C[(size_t)m * N + n] = acc[i][j] + (bias ? bias[n] : 0.f);
        }
    }
}

__global__ void __launch_bounds__(256) sgemm_att_kernel(const float* A, const float* B,
                                                        const float* bias, int M) {
    sgemm_body<128, 128, 8, 8, 8>(A, B, bias, g_att, M, EDIM, EDIM);
}
__global__ void __launch_bounds__(256) sgemm_gates_kernel() {
    sgemm_body<64, 64, 8, 4, 4>(g_z, g_Wg, g_bg, g_gates, BATCH, GDIM, KZ);
}
__global__ void __launch_bounds__(256) sgemm_logits_kernel(const float* B, const float* bias,
                                                           float* C) {
    sgemm_body<128, 128, 8, 8, 8>(g_h, B, bias, C, BATCH, VDIM, EDIM);
}

// ---------------- per-step attention + z assembly ----------------
__global__ void attn_kernel(const float* __restrict__ enc,
                            const float* __restrict__ emb,
                            const int* __restrict__ counts) {
    int b = blockIdx.x, t = threadIdx.x;
    int lane = t & 31, w = t >> 5;
    __shared__ float sh[EDIM];
    __shared__ float sc[CMAX];
    __shared__ float red[256];

    sh[t]       = g_h[b * EDIM + t];
    sh[t + 256] = g_h[b * EDIM + t + 256];
    __syncthreads();

    int cnt = counts[b], off = g_off[b];

    // scores: one context per warp, round-robin
    for (int c = w; c < cnt; c += 8) {
        const float* row = g_att + (size_t)(off + c) * EDIM;
        float s = 0.f;
#pragma unroll
        for (int j = 0; j < EDIM; j += 128) {
            float4 v = *(const float4*)(row + j + lane * 4);
            s += v.x * sh[j + lane * 4]     + v.y * sh[j + lane * 4 + 1]
               + v.z * sh[j + lane * 4 + 2] + v.w * sh[j + lane * 4 + 3];
        }
#pragma unroll
        for (int o = 16; o; o >>= 1) s += __shfl_xor_sync(0xFFFFFFFFu, s, o);
        if (lane == 0) sc[c] = s;
    }
    __syncthreads();

    // softmax: max
    float m = -3.4e38f;
    for (int c = t; c < cnt; c += 256) m = fmaxf(m, sc[c]);
    red[t] = m;
    __syncthreads();
    for (int d = 128; d; d >>= 1) {
        if (t < d) red[t] = fmaxf(red[t], red[t + d]);
        __syncthreads();
    }
    float mx = red[0];
    __syncthreads();

    // exp + sum
    float s = 0.f;
    for (int c = t; c < cnt; c += 256) {
        float e = expf(sc[c] - mx);
        sc[c] = e;
        s += e;
    }
    red[t] = s;
    __syncthreads();
    for (int d = 128; d; d >>= 1) {
        if (t < d) red[t] += red[t + d];
        __syncthreads();
    }
    float inv = 1.f / red[0];

    // attended: each thread owns 2 columns
    float2 acc = make_float2(0.f, 0.f);
    for (int c = 0; c < cnt; c++) {
        float wgt = sc[c];
        float2 v = *(const float2*)(enc + (size_t)(off + c) * EDIM + 2 * t);
        acc.x += wgt * v.x;
        acc.y += wgt * v.y;
    }
    float* z = g_z + (size_t)b * KZ;
    z[512 + 2 * t]     = acc.x * inv;
    z[512 + 2 * t + 1] = acc.y * inv;

    int tok = g_cur[b];
    z[t]        = emb[(size_t)tok * EDIM + t];
    z[t + 256]  = emb[(size_t)tok * EDIM + t + 256];
    z[1024 + t]       = sh[t];
    z[1024 + 256 + t] = sh[t + 256];
}

// ---------------- LSTM pointwise ----------------
__global__ void lstm_kernel() {
    int idx = blockIdx.x * blockDim.x + threadIdx.x;   // BATCH*EDIM
    int b = idx >> 9, e = idx & 511;
    const float* g = g_gates + (size_t)b * GDIM;
    float gi = g[e], gf = g[512 + e], gg = g[1024 + e], go = g[1536 + e];
    float si = 1.f / (1.f + expf(-gi));
    float sf = 1.f / (1.f + expf(-gf));
    float so = 1.f / (1.f + expf(-go));
    float cn = sf * g_c[idx] + si * tanhf(gg);
    float hn = so * tanhf(cn);
    g_c[idx] = cn;
    g_h[idx] = hn;
}

// ---------------- argmax with first-index tie-break ----------------
__global__ void argmax_kernel(const float* __restrict__ logits) {
    int b = blockIdx.x, t = threadIdx.x;
    const float* row = logits + (size_t)b * VDIM;
    float best = -3.4e38f;
    int bi = VDIM;
    for (int j = t; j < VDIM; j += 256) {
        float v = row[j];
        if (v > best) { best = v; bi = j; }   // j ascending -> first max per thread
    }
    __shared__ float sv[256];
    __shared__ int si[256];
    sv[t] = best; si[t] = bi;
    __syncthreads();
    for (int d = 128; d; d >>= 1) {
        if (t < d) {
            if (sv[t + d] > sv[t] || (sv[t + d] == sv[t] && si[t + d] < si[t])) {
                sv[t] = sv[t + d];
                si[t] = si[t + d];
            }
        }
        __syncthreads();
    }
    if (t == 0) g_cur[b] = si[0];
}

// ---------------- launch ----------------
extern "C" void kernel_launch(void* const* d_in, const int* in_sizes, int n_in,
                              void* d_out, int out_size) {
    const float* enc    = (const float*)d_in[0];
    const int*   tl     = (const int*)d_in[1];
    const int*   counts = (const int*)d_in[2];
    const float* emb    = (const float*)d_in[3];
    const float* attn_W = (const float*)d_in[4];
    const float* attn_b = (const float*)d_in[5];
    const float* W_ih   = (const float*)d_in[6];
    const float* W_hh   = (const float*)d_in[7];
    const float* b_ih   = (const float*)d_in[8];
    const float* b_hh   = (const float*)d_in[9];
    const float* proj_W = (const float*)d_in[10];
    const float* proj_b = (const float*)d_in[11];
    float* out = (float*)d_out;
    int n_paths = in_sizes[0] / EDIM;

    // step 0 output is zeros
    zero_kernel<<<2048, 256>>>((float4*)out, BATCH * VDIM / 4);
    init_meta_kernel<<<1, BATCH>>>(counts, tl);
    build_wg_kernel<<<(KZ * GDIM + 255) / 256, 256>>>(W_ih, W_hh, b_ih, b_hh);

    // att_paths = encoded_paths @ attn_W + attn_b
    {
        dim3 grid(EDIM / 128, (n_paths + 127) / 128);
        sgemm_att_kernel<<<grid, 256>>>(enc, attn_W, attn_b, n_paths);
    }
    init_h_kernel<<<BATCH, 256>>>(enc, counts);

    dim3 grid_gates(GDIM / 64, BATCH / 64);
    dim3 grid_logits((VDIM + 127) / 128, BATCH / 128);

    for (int t = 1; t < LSTEPS; t++) {
        attn_kernel<<<BATCH, 256>>>(enc, emb, counts);
        sgemm_gates_kernel<<<grid_gates, 256>>>();
        lstm_kernel<<<BATCH * EDIM / 256, 256>>>();
        float* logits = out + (size_t)t * BATCH * VDIM;
        sgemm_logits_kernel<<<grid_logits, 256>>>(proj_W, proj_b, logits);
        if (t < LSTEPS - 1) argmax_kernel<<<BATCH, 256>>>(logits);
    }
}

// round 4
// speedup vs baseline: 1.4521x; 1.4521x over previous
#include <cuda_runtime.h>
#include <cuda_bf16.h>
#include <math.h>
#include <stdint.h>

// ---------------- problem constants ----------------
#define BATCH 256
#define EDIM  512
#define VDIM  27000
#define VPAD  27008
#define LSTEPS 16
#define CMAX  200
#define KZ    1536   // z = [emb(512) | attended(512) | h(512)]
#define GDIM  2048   // 4*E

#define PLANE_B ((size_t)VPAD * EDIM)      // proj limb plane
#define PLANE_W ((size_t)GDIM * KZ)        // gate-weight limb plane
#define PLANE_Z ((size_t)BATCH * KZ)       // z limb plane
#define PLANE_H ((size_t)BATCH * EDIM)     // h limb plane

// ---------------- persistent device scratch ----------------
__device__ __align__(128) float g_att[32768 * EDIM];
__device__ __align__(128) float g_h[BATCH * EDIM];
__device__ __align__(128) float g_c[BATCH * EDIM];
__device__ __align__(128) float g_gates[BATCH * GDIM];
__device__ __align__(128) float g_bg[GDIM];
__device__ int   g_off[BATCH + 1];
__device__ int   g_cur[BATCH];
__device__ __align__(128) __nv_bfloat16 g_B3[3 * PLANE_B];   // proj_W^T limbs [VPAD][512]
__device__ __align__(128) __nv_bfloat16 g_W3[3 * PLANE_W];   // [W_ih|W_hh] limbs [2048][1536]
__device__ __align__(128) __nv_bfloat16 g_z3[3 * PLANE_Z];   // z limbs [256][1536]
__device__ __align__(128) __nv_bfloat16 g_h3[3 * PLANE_H];   // h limbs [256][512]

// limb-product pair schedule: hh, hm, mh, hl, lh, mm
__device__ const int g_pa[6] = {0, 0, 1, 0, 2, 1};
__device__ const int g_pb[6] = {0, 1, 0, 2, 0, 1};

// ---------------- helpers ----------------
__device__ __forceinline__ uint32_t smem_u32(const void* p) {
    uint32_t a;
    asm("{ .reg .u64 t; cvta.to.shared.u64 t, %1; cvt.u32.u64 %0, t; }" : "=r"(a) : "l"(p));
    return a;
}

__device__ __forceinline__ void split3_store(float v, __nv_bfloat16* base, size_t off, size_t plane) {
    __nv_bfloat16 h = __float2bfloat16(v);
    float r1 = v - __bfloat162float(h);
    __nv_bfloat16 m = __float2bfloat16(r1);
    float r2 = r1 - __bfloat162float(m);
    __nv_bfloat16 l = __float2bfloat16(r2);
    base[off]             = h;
    base[off + plane]     = m;
    base[off + 2 * plane] = l;
}

__device__ __forceinline__ void ldmatrix_x4(uint32_t* r, uint32_t addr) {
    asm volatile("ldmatrix.sync.aligned.m8n8.x4.shared.b16 {%0,%1,%2,%3}, [%4];"
                 : "=r"(r[0]), "=r"(r[1]), "=r"(r[2]), "=r"(r[3]) : "r"(addr) : "memory");
}

__device__ __forceinline__ void mma16816(float* c, const uint32_t* a, uint32_t b0, uint32_t b1) {
    asm volatile(
        "mma.sync.aligned.m16n8k16.row.col.f32.bf16.bf16.f32 "
        "{%0,%1,%2,%3}, {%4,%5,%6,%7}, {%8,%9}, {%0,%1,%2,%3};"
        : "+f"(c[0]), "+f"(c[1]), "+f"(c[2]), "+f"(c[3])
        : "r"(a[0]), "r"(a[1]), "r"(a[2]), "r"(a[3]), "r"(b0), "r"(b1));
}

// ---------------- init: offsets prefix sum + initial tokens ----------------
__global__ void init_meta_kernel(const int* __restrict__ counts,
                                 const int* __restrict__ target_labels) {
    __shared__ int s[BATCH];
    int t = threadIdx.x;
    s[t] = counts[t];
    __syncthreads();
    for (int d = 1; d < BATCH; d <<= 1) {
        int v = (t >= d) ? s[t - d] : 0;
        __syncthreads();
        s[t] += v;
        __syncthreads();
    }
    g_off[t] = s[t] - counts[t];
    if (t == 0) g_off[BATCH] = s[BATCH - 1];
    g_cur[t] = target_labels[t];
}

// ---------------- build fused gate weights (3 bf16 limb planes) ----------------
__global__ void build_wg3_kernel(const float* __restrict__ W_ih,
                                 const float* __restrict__ W_hh,
                                 const float* __restrict__ b_ih,
                                 const float* __restrict__ b_hh) {
    int i = blockIdx.x * blockDim.x + threadIdx.x;
    if (i < GDIM * KZ) {
        int n = i / KZ, k = i % KZ;
        float v = (k < 1024) ? W_ih[(size_t)n * 1024 + k]
                             : W_hh[(size_t)n * 512 + (k - 1024)];
        split3_store(v, g_W3, (size_t)n * KZ + k, PLANE_W);
    }
    if (i < GDIM) g_bg[i] = b_ih[i] + b_hh[i];
}

// ---------------- build proj_W^T limb planes [VPAD][512] ----------------
__global__ void prepB3_kernel(const float* __restrict__ W) {
    __shared__ float tile[32][33];
    int n0 = blockIdx.x * 32, k0 = blockIdx.y * 32;
    int tx = threadIdx.x, ty = threadIdx.y;  // 32 x 8
#pragma unroll
    for (int i = 0; i < 4; i++) {
        int k = k0 + ty + i * 8, n = n0 + tx;
        tile[ty + i * 8][tx] = (n < VDIM) ? W[(size_t)k * VDIM + n] : 0.f;
    }
    __syncthreads();
#pragma unroll
    for (int i = 0; i < 4; i++) {
        int n = n0 + ty + i * 8, kk = k0 + tx;
        split3_store(tile[tx][ty + i * 8], g_B3, (size_t)n * EDIM + kk, PLANE_B);
    }
}

// ---------------- init h0 = c0 = mean of contexts ----------------
__global__ void init_h_kernel(const float* __restrict__ enc,
                              const int* __restrict__ counts) {
    int b = blockIdx.x, t = threadIdx.x;
    int cnt = counts[b], off = g_off[b];
    float2 acc = make_float2(0.f, 0.f);
    for (int c = 0; c < cnt; c++) {
        float2 v = *(const float2*)(enc + (size_t)(off + c) * EDIM + 2 * t);
        acc.x += v.x; acc.y += v.y;
    }
    float inv = 1.f / (float)cnt;
    float h0 = acc.x * inv, h1 = acc.y * inv;
    g_h[b * EDIM + 2 * t]     = h0;  g_c[b * EDIM + 2 * t]     = h0;
    g_h[b * EDIM + 2 * t + 1] = h1;  g_c[b * EDIM + 2 * t + 1] = h1;
}

// ---------------- zero the step-0 output slab ----------------
__global__ void zero_kernel(float4* __restrict__ p, int n4) {
    for (int i = blockIdx.x * blockDim.x + threadIdx.x; i < n4; i += gridDim.x * blockDim.x)
        p[i] = make_float4(0.f, 0.f, 0.f, 0.f);
}

// ---------------- fp32 SGEMM (att precompute only) ----------------
__global__ void __launch_bounds__(256) sgemm_att_kernel(const float* __restrict__ A,
                                                        const float* __restrict__ B,
                                                        const float* __restrict__ bias, int M) {
    const int BM = 128, BN = 128, BK = 8, TM = 8, TN = 8;
    const int N = EDIM, K = EDIM;
    __shared__ float As[BK][BM];
    __shared__ float Bs[BK][BN];
    int tid = threadIdx.x;
    int bn0 = blockIdx.x * BN;
    int bm0 = blockIdx.y * BM;
    int tx = tid % (BN / TN);
    int ty = tid / (BN / TN);
    float acc[TM][TN];
#pragma unroll
    for (int i = 0; i < TM; i++)
#pragma unroll
        for (int j = 0; j < TN; j++) acc[i][j] = 0.f;

    for (int k0 = 0; k0 < K; k0 += BK) {
#pragma unroll
        for (int i = tid * 4; i < BM * BK; i += 256 * 4) {
            int r = i / BK, kk = i % BK;
            int m = bm0 + r;
            float4 v = make_float4(0.f, 0.f, 0.f, 0.f);
            if (m < M) v = *(const float4*)(A + (size_t)m * K + k0 + kk);
            As[kk + 0][r] = v.x; As[kk + 1][r] = v.y;
            As[kk + 2][r] = v.z; As[kk + 3][r] = v.w;
        }
#pragma unroll
        for (int i = tid * 4; i < BK * BN; i += 256 * 4) {
            int r = i / BN, cc = i % BN;
            *(float4*)&Bs[r][cc] = *(const float4*)(B + (size_t)(k0 + r) * N + bn0 + cc);
        }
        __syncthreads();
#pragma unroll
        for (int k = 0; k < BK; k++) {
            float ra[TM], rb[TN];
#pragma unroll
            for (int i = 0; i < TM; i += 4)
                *(float4*)&ra[i] = *(const float4*)&As[k][ty * TM + i];
#pragma unroll
            for (int j = 0; j < TN; j += 4)
                *(float4*)&rb[j] = *(const float4*)&Bs[k][tx * TN + j];
#pragma unroll
            for (int i = 0; i < TM; i++)
#pragma unroll
                for (int j = 0; j < TN; j++)
                    acc[i][j] += ra[i] * rb[j];
        }
        __syncthreads();
    }
#pragma unroll
    for (int i = 0; i < TM; i++) {
        int m = bm0 + ty * TM + i;
        if (m >= M) continue;
#pragma unroll
        for (int j = 0; j < TN; j++)
            g_att[(size_t)m * N + bn0 + tx * TN + j] = acc[i][j] + bias[bn0 + tx * TN + j];
    }
}

// ================= HMMA GEMM (3-limb bf16, 6 products) =================
// C[256, N] = sum_p A_limb[pa[p]] @ B_limb[pb[p]]^T  (+bias)
// BM=128, BN=64, BK=64; 8 warps (4x2); warp tile 32x32.
__global__ void __launch_bounds__(256) hmma_kernel(const __nv_bfloat16* __restrict__ Ab,
                                                   const __nv_bfloat16* __restrict__ Bb,
                                                   size_t planeA, size_t planeB, int K,
                                                   const float* __restrict__ bias,
                                                   float* __restrict__ out,
                                                   int ldo, int Nvalid) {
    __shared__ __align__(128) char sAraw[128 * 128];   // 128 rows x 128B
    __shared__ __align__(128) char sBraw[64 * 128];    // 64 rows x 128B
    uint32_t sA = smem_u32(sAraw);
    uint32_t sB = smem_u32(sBraw);

    int tid = threadIdx.x, lane = tid & 31, warp = tid >> 5;
    int warpM = warp >> 1, warpN = warp & 1;
    int bm0 = blockIdx.y * 128;
    int n0  = blockIdx.x * 64;

    // ldmatrix row/col-half indices (lane-dependent, chunk-invariant)
    int rAl[2], rBl[2];
#pragma unroll
    for (int mt = 0; mt < 2; mt++)
        rAl[mt] = warpM * 32 + mt * 16 + (lane & 7) + ((lane >> 3) & 1) * 8;
#pragma unroll
    for (int nt = 0; nt < 2; nt++)
        rBl[nt] = warpN * 32 + nt * 16 + (lane & 7) + (lane >> 4) * 8;
    int clA = lane >> 4;
    int clB = (lane >> 3) & 1;

    float acc[2][4][4];
#pragma unroll
    for (int a = 0; a < 2; a++)
#pragma unroll
        for (int b = 0; b < 4; b++)
#pragma unroll
            for (int c = 0; c < 4; c++) acc[a][b][c] = 0.f;

    const int KC = K >> 6;          // 64-wide chunks per limb plane
    const int NC = 6 * KC;

    uint4 pA[4], pB[2];
    // prefetch chunk 0
    {
        const __nv_bfloat16* Ap = Ab;       // pa[0]=0
        const __nv_bfloat16* Bp = Bb;       // pb[0]=0
#pragma unroll
        for (int i = 0; i < 4; i++) {
            int li = i * 256 + tid, r = li >> 3, c = li & 7;
            pA[i] = *(const uint4*)(Ap + (size_t)(bm0 + r) * K + c * 8);
        }
#pragma unroll
        for (int i = 0; i < 2; i++) {
            int li = i * 256 + tid, r = li >> 3, c = li & 7;
            pB[i] = *(const uint4*)(Bp + (size_t)(n0 + r) * K + c * 8);
        }
    }
    // store chunk 0
#pragma unroll
    for (int i = 0; i < 4; i++) {
        int li = i * 256 + tid, r = li >> 3, c = li & 7;
        *(uint4*)(sAraw + r * 128 + ((c ^ (r & 7)) << 4)) = pA[i];
    }
#pragma unroll
    for (int i = 0; i < 2; i++) {
        int li = i * 256 + tid, r = li >> 3, c = li & 7;
        *(uint4*)(sBraw + r * 128 + ((c ^ (r & 7)) << 4)) = pB[i];
    }

    for (int kk = 0; kk < NC; kk++) {
        __syncthreads();   // smem tiles for chunk kk are visible

        // prefetch chunk kk+1 into registers
        if (kk + 1 < NC) {
            int p  = (kk + 1) / KC;
            int k0 = ((kk + 1) - p * KC) << 6;
            const __nv_bfloat16* Ap = Ab + (size_t)g_pa[p] * planeA;
            const __nv_bfloat16* Bp = Bb + (size_t)g_pb[p] * planeB;
#pragma unroll
            for (int i = 0; i < 4; i++) {
                int li = i * 256 + tid, r = li >> 3, c = li & 7;
                pA[i] = *(const uint4*)(Ap + (size_t)(bm0 + r) * K + k0 + c * 8);
            }
#pragma unroll
            for (int i = 0; i < 2; i++) {
                int li = i * 256 + tid, r = li >> 3, c = li & 7;
                pB[i] = *(const uint4*)(Bp + (size_t)(n0 + r) * K + k0 + c * 8);
            }
        }

        // compute on chunk kk
#pragma unroll
        for (int h = 0; h < 4; h++) {
            uint32_t af[2][4], bf[2][4];
#pragma unroll
            for (int mt = 0; mt < 2; mt++) {
                int r = rAl[mt];
                int c = (h * 2 + clA) ^ (r & 7);
                ldmatrix_x4(af[mt], sA + r * 128 + (c << 4));
            }
#pragma unroll
            for (int nt = 0; nt < 2; nt++) {
                int r = rBl[nt];
                int c = (h * 2 + clB) ^ (r & 7);
                ldmatrix_x4(bf[nt], sB + r * 128 + (c << 4));
            }
#pragma unroll
            for (int mt = 0; mt < 2; mt++)
#pragma unroll
                for (int nt = 0; nt < 2; nt++)
#pragma unroll
                    for (int j = 0; j < 2; j++)
                        mma16816(acc[mt][nt * 2 + j], af[mt], bf[nt][2 * j], bf[nt][2 * j + 1]);
        }

        __syncthreads();   // all warps done reading smem

        if (kk + 1 < NC) {
#pragma unroll
            for (int i = 0; i < 4; i++) {
                int li = i * 256 + tid, r = li >> 3, c = li & 7;
                *(uint4*)(sAraw + r * 128 + ((c ^ (r & 7)) << 4)) = pA[i];
            }
#pragma unroll
            for (int i = 0; i < 2; i++) {
                int li = i * 256 + tid, r = li >> 3, c = li & 7;
                *(uint4*)(sBraw + r * 128 + ((c ^ (r & 7)) << 4)) = pB[i];
            }
        }
    }

    // epilogue: bias + store
#pragma unroll
    for (int mt = 0; mt < 2; mt++) {
        int row0 = bm0 + warpM * 32 + mt * 16 + (lane >> 2);
#pragma unroll
        for (int n8 = 0; n8 < 4; n8++) {
            int col = n0 + warpN * 32 + n8 * 8 + (lane & 3) * 2;
            if (col < Nvalid) {
                float2 bv = *(const float2*)(bias + col);
                float2 v0 = make_float2(acc[mt][n8][0] + bv.x, acc[mt][n8][1] + bv.y);
                float2 v1 = make_float2(acc[mt][n8][2] + bv.x, acc[mt][n8][3] + bv.y);
                *(float2*)(out + (size_t)row0 * ldo + col)       = v0;
                *(float2*)(out + (size_t)(row0 + 8) * ldo + col) = v1;
            }
        }
    }
}

// ---------------- per-step attention + z assembly (writes z limb planes) ----------------
__global__ void attn_kernel(const float* __restrict__ enc,
                            const float* __restrict__ emb,
                            const int* __restrict__ counts) {
    int b = blockIdx.x, t = threadIdx.x;
    int lane = t & 31, w = t >> 5;
    __shared__ float sh[EDIM];
    __shared__ float sc[CMAX];
    __shared__ float red[256];

    sh[t]       = g_h[b * EDIM + t];
    sh[t + 256] = g_h[b * EDIM + t + 256];
    __syncthreads();

    int cnt = counts[b], off = g_off[b];

    for (int c = w; c < cnt; c += 8) {
        const float* row = g_att + (size_t)(off + c) * EDIM;
        float s = 0.f;
#pragma unroll
        for (int j = 0; j < EDIM; j += 128) {
            float4 v = *(const float4*)(row + j + lane * 4);
            s += v.x * sh[j + lane * 4]     + v.y * sh[j + lane * 4 + 1]
               + v.z * sh[j + lane * 4 + 2] + v.w * sh[j + lane * 4 + 3];
        }
#pragma unroll
        for (int o = 16; o; o >>= 1) s += __shfl_xor_sync(0xFFFFFFFFu, s, o);
        if (lane == 0) sc[c] = s;
    }
    __syncthreads();

    float m = -3.4e38f;
    for (int c = t; c < cnt; c += 256) m = fmaxf(m, sc[c]);
    red[t] = m;
    __syncthreads();
    for (int d = 128; d; d >>= 1) {
        if (t < d) red[t] = fmaxf(red[t], red[t + d]);
        __syncthreads();
    }
    float mx = red[0];
    __syncthreads();

    float s = 0.f;
    for (int c = t; c < cnt; c += 256) {
        float e = expf(sc[c] - mx);
        sc[c] = e;
        s += e;
    }
    red[t] = s;
    __syncthreads();
    for (int d = 128; d; d >>= 1) {
        if (t < d) red[t] += red[t + d];
        __syncthreads();
    }
    float inv = 1.f / red[0];

    float2 acc = make_float2(0.f, 0.f);
    for (int c = 0; c < cnt; c++) {
        float wgt = sc[c];
        float2 v = *(const float2*)(enc + (size_t)(off + c) * EDIM + 2 * t);
        acc.x += wgt * v.x;
        acc.y += wgt * v.y;
    }
    size_t zr = (size_t)b * KZ;
    split3_store(acc.x * inv, g_z3, zr + 512 + 2 * t,     PLANE_Z);
    split3_store(acc.y * inv, g_z3, zr + 512 + 2 * t + 1, PLANE_Z);

    int tok = g_cur[b];
    split3_store(emb[(size_t)tok * EDIM + t],       g_z3, zr + t,       PLANE_Z);
    split3_store(emb[(size_t)tok * EDIM + t + 256], g_z3, zr + t + 256, PLANE_Z);
    split3_store(sh[t],       g_z3, zr + 1024 + t,       PLANE_Z);
    split3_store(sh[t + 256], g_z3, zr + 1024 + 256 + t, PLANE_Z);
}

// ---------------- LSTM pointwise (+ h limb split for logits GEMM) ----------------
__global__ void lstm_kernel() {
    int idx = blockIdx.x * blockDim.x + threadIdx.x;
    int b = idx >> 9, e = idx & 511;
    const float* g = g_gates + (size_t)b * GDIM;
    float gi = g[e], gf = g[512 + e], gg = g[1024 + e], go = g[1536 + e];
    float si = 1.f / (1.f + expf(-gi));
    float sf = 1.f / (1.f + expf(-gf));
    float so = 1.f / (1.f + expf(-go));
    float cn = sf * g_c[idx] + si * tanhf(gg);
    float hn = so * tanhf(cn);
    g_c[idx] = cn;
    g_h[idx] = hn;
    split3_store(hn, g_h3, (size_t)idx, PLANE_H);
}

// ---------------- argmax with first-index tie-break ----------------
__global__ void argmax_kernel(const float* __restrict__ logits) {
    int b = blockIdx.x, t = threadIdx.x;
    const float* row = logits + (size_t)b * VDIM;
    float best = -3.4e38f;
    int bi = VDIM;
    for (int j = t; j < VDIM; j += 256) {
        float v = row[j];
        if (v > best) { best = v; bi = j; }
    }
    __shared__ float sv[256];
    __shared__ int si[256];
    sv[t] = best; si[t] = bi;
    __syncthreads();
    for (int d = 128; d; d >>= 1) {
        if (t < d) {
            if (sv[t + d] > sv[t] || (sv[t + d] == sv[t] && si[t + d] < si[t])) {
                sv[t] = sv[t + d];
                si[t] = si[t + d];
            }
        }
        __syncthreads();
    }
    if (t == 0) g_cur[b] = si[0];
}

// ---------------- launch ----------------
extern "C" void kernel_launch(void* const* d_in, const int* in_sizes, int n_in,
                              void* d_out, int out_size) {
    const float* enc    = (const float*)d_in[0];
    const int*   tl     = (const int*)d_in[1];
    const int*   counts = (const int*)d_in[2];
    const float* emb    = (const float*)d_in[3];
    const float* attn_W = (const float*)d_in[4];
    const float* attn_b = (const float*)d_in[5];
    const float* W_ih   = (const float*)d_in[6];
    const float* W_hh   = (const float*)d_in[7];
    const float* b_ih   = (const float*)d_in[8];
    const float* b_hh   = (const float*)d_in[9];
    const float* proj_W = (const float*)d_in[10];
    const float* proj_b = (const float*)d_in[11];
    float* out = (float*)d_out;
    int n_paths = in_sizes[0] / EDIM;

    // resolve device-global addresses for kernel args
    __nv_bfloat16 *pB3, *pW3, *pZ3, *pH3;
    float *pGates, *pBg;
    cudaGetSymbolAddress((void**)&pB3, g_B3);
    cudaGetSymbolAddress((void**)&pW3, g_W3);
    cudaGetSymbolAddress((void**)&pZ3, g_z3);
    cudaGetSymbolAddress((void**)&pH3, g_h3);
    cudaGetSymbolAddress((void**)&pGates, g_gates);
    cudaGetSymbolAddress((void**)&pBg, g_bg);

    zero_kernel<<<2048, 256>>>((float4*)out, BATCH * VDIM / 4);
    init_meta_kernel<<<1, BATCH>>>(counts, tl);
    build_wg3_kernel<<<(GDIM * KZ + 255) / 256, 256>>>(W_ih, W_hh, b_ih, b_hh);
    {
        dim3 grid(VPAD / 32, EDIM / 32);
        prepB3_kernel<<<grid, dim3(32, 8)>>>(proj_W);
    }
    {
        dim3 grid(EDIM / 128, (n_paths + 127) / 128);
        sgemm_att_kernel<<<grid, 256>>>(enc, attn_W, attn_b, n_paths);
    }
    init_h_kernel<<<BATCH, 256>>>(enc, counts);

    dim3 grid_gates(GDIM / 64, 2);
    dim3 grid_logits(VPAD / 64, 2);

    for (int t = 1; t < LSTEPS; t++) {
        attn_kernel<<<BATCH, 256>>>(enc, emb, counts);
        hmma_kernel<<<grid_gates, 256>>>(pZ3, pW3, PLANE_Z, PLANE_W, KZ,
                                         pBg, pGates, GDIM, GDIM);
        lstm_kernel<<<BATCH * EDIM / 256, 256>>>();
        float* logits = out + (size_t)t * BATCH * VDIM;
        hmma_kernel<<<grid_logits, 256>>>(pH3, pB3, PLANE_H, PLANE_B, EDIM,
                                          proj_b, logits, VDIM, VDIM);
        if (t < LSTEPS - 1) argmax_kernel<<<BATCH, 256>>>(logits);
    }
}

// round 5
// speedup vs baseline: 1.6706x; 1.1505x over previous
#include <cuda_runtime.h>
#include <cuda_fp16.h>
#include <math.h>
#include <stdint.h>

// ---------------- problem constants ----------------
#define BATCH 256
#define EDIM  512
#define VDIM  27000
#define VPAD  27008
#define LSTEPS 16
#define CMAX  200
#define KZ    1536   // z = [emb(512) | attended(512) | h(512)]
#define GDIM  2048   // 4*E

#define PLANE_B  ((size_t)VPAD * EDIM)     // proj limb plane
#define PLANE_W  ((size_t)GDIM * KZ)       // gate-weight limb plane
#define PLANE_Z  ((size_t)BATCH * KZ)      // z limb plane
#define PLANE_H  ((size_t)BATCH * EDIM)    // h limb plane
#define PLANE_E  ((size_t)32768 * EDIM)    // encoded-paths limb plane
#define PLANE_AW ((size_t)EDIM * EDIM)     // attn_W^T limb plane

// ---------------- persistent device scratch ----------------
__device__ __align__(128) float g_att[32768 * EDIM];
__device__ __align__(128) float g_h[BATCH * EDIM];
__device__ __align__(128) float g_c[BATCH * EDIM];
__device__ __align__(128) float g_gates[BATCH * GDIM];
__device__ __align__(128) float g_bg[GDIM];
__device__ int   g_off[BATCH + 1];
__device__ int   g_cur[BATCH];
__device__ __align__(128) __half g_B2[2 * PLANE_B];    // proj_W^T limbs [VPAD][512]
__device__ __align__(128) __half g_W2[2 * PLANE_W];    // [W_ih|W_hh] limbs [2048][1536]
__device__ __align__(128) __half g_z2[2 * PLANE_Z];    // z limbs [256][1536]
__device__ __align__(128) __half g_h2[2 * PLANE_H];    // h limbs [256][512]
__device__ __align__(128) __half g_E2[2 * PLANE_E];    // enc limbs [n_paths][512]
__device__ __align__(128) __half g_AW2[2 * PLANE_AW];  // attn_W^T limbs [512][512]

// limb-product pair schedule: hh, hm, mh
__device__ const int g_pa[3] = {0, 0, 1};
__device__ const int g_pb[3] = {0, 1, 0};

// ---------------- helpers ----------------
__device__ __forceinline__ uint32_t smem_u32(const void* p) {
    uint32_t a;
    asm("{ .reg .u64 t; cvta.to.shared.u64 t, %1; cvt.u32.u64 %0, t; }" : "=r"(a) : "l"(p));
    return a;
}

__device__ __forceinline__ void split2_store(float v, __half* base, size_t off, size_t plane) {
    __half h = __float2half_rn(v);
    float r = v - __half2float(h);
    base[off]         = h;
    base[off + plane] = __float2half_rn(r);
}

__device__ __forceinline__ void ldmatrix_x4(uint32_t* r, uint32_t addr) {
    asm volatile("ldmatrix.sync.aligned.m8n8.x4.shared.b16 {%0,%1,%2,%3}, [%4];"
                 : "=r"(r[0]), "=r"(r[1]), "=r"(r[2]), "=r"(r[3]) : "r"(addr) : "memory");
}

__device__ __forceinline__ void mma16816(float* c, const uint32_t* a, uint32_t b0, uint32_t b1) {
    asm volatile(
        "mma.sync.aligned.m16n8k16.row.col.f32.f16.f16.f32 "
        "{%0,%1,%2,%3}, {%4,%5,%6,%7}, {%8,%9}, {%0,%1,%2,%3};"
        : "+f"(c[0]), "+f"(c[1]), "+f"(c[2]), "+f"(c[3])
        : "r"(a[0]), "r"(a[1]), "r"(a[2]), "r"(a[3]), "r"(b0), "r"(b1));
}

// ---------------- init: offsets prefix sum + initial tokens ----------------
__global__ void init_meta_kernel(const int* __restrict__ counts,
                                 const int* __restrict__ target_labels) {
    __shared__ int s[BATCH];
    int t = threadIdx.x;
    s[t] = counts[t];
    __syncthreads();
    for (int d = 1; d < BATCH; d <<= 1) {
        int v = (t >= d) ? s[t - d] : 0;
        __syncthreads();
        s[t] += v;
        __syncthreads();
    }
    g_off[t] = s[t] - counts[t];
    if (t == 0) g_off[BATCH] = s[BATCH - 1];
    g_cur[t] = target_labels[t];
}

// ---------------- build fused gate weights (2 fp16 limb planes) ----------------
__global__ void build_wg2_kernel(const float* __restrict__ W_ih,
                                 const float* __restrict__ W_hh,
                                 const float* __restrict__ b_ih,
                                 const float* __restrict__ b_hh) {
    int i = blockIdx.x * blockDim.x + threadIdx.x;
    if (i < GDIM * KZ) {
        int n = i / KZ, k = i % KZ;
        float v = (k < 1024) ? W_ih[(size_t)n * 1024 + k]
                             : W_hh[(size_t)n * 512 + (k - 1024)];
        split2_store(v, g_W2, (size_t)n * KZ + k, PLANE_W);
    }
    if (i < GDIM) g_bg[i] = b_ih[i] + b_hh[i];
}

// ---------------- build proj_W^T limb planes [VPAD][512] ----------------
__global__ void prepB2_kernel(const float* __restrict__ W) {
    __shared__ float tile[32][33];
    int n0 = blockIdx.x * 32, k0 = blockIdx.y * 32;
    int tx = threadIdx.x, ty = threadIdx.y;  // 32 x 8
#pragma unroll
    for (int i = 0; i < 4; i++) {
        int k = k0 + ty + i * 8, n = n0 + tx;
        tile[ty + i * 8][tx] = (n < VDIM) ? W[(size_t)k * VDIM + n] : 0.f;
    }
    __syncthreads();
#pragma unroll
    for (int i = 0; i < 4; i++) {
        int n = n0 + ty + i * 8, kk = k0 + tx;
        split2_store(tile[tx][ty + i * 8], g_B2, (size_t)n * EDIM + kk, PLANE_B);
    }
}

// ---------------- build attn_W^T limb planes [512][512] ----------------
__global__ void prepAW2_kernel(const float* __restrict__ W) {
    __shared__ float tile[32][33];
    int n0 = blockIdx.x * 32, k0 = blockIdx.y * 32;
    int tx = threadIdx.x, ty = threadIdx.y;
#pragma unroll
    for (int i = 0; i < 4; i++)
        tile[ty + i * 8][tx] = W[(size_t)(k0 + ty + i * 8) * EDIM + n0 + tx];
    __syncthreads();
#pragma unroll
    for (int i = 0; i < 4; i++)
        split2_store(tile[tx][ty + i * 8], g_AW2,
                     (size_t)(n0 + ty + i * 8) * EDIM + k0 + tx, PLANE_AW);
}

// ---------------- split encoded_paths into fp16 limbs ----------------
__global__ void prepE2_kernel(const float* __restrict__ enc, int n_elem) {
    int i = blockIdx.x * blockDim.x + threadIdx.x;
    if (i < n_elem) split2_store(enc[i], g_E2, (size_t)i, PLANE_E);
}

// ---------------- init h0 = c0 = mean of contexts ----------------
__global__ void init_h_kernel(const float* __restrict__ enc,
                              const int* __restrict__ counts) {
    int b = blockIdx.x, t = threadIdx.x;
    int cnt = counts[b], off = g_off[b];
    float2 acc = make_float2(0.f, 0.f);
    for (int c = 0; c < cnt; c++) {
        float2 v = *(const float2*)(enc + (size_t)(off + c) * EDIM + 2 * t);
        acc.x += v.x; acc.y += v.y;
    }
    float inv = 1.f / (float)cnt;
    float h0 = acc.x * inv, h1 = acc.y * inv;
    g_h[b * EDIM + 2 * t]     = h0;  g_c[b * EDIM + 2 * t]     = h0;
    g_h[b * EDIM + 2 * t + 1] = h1;  g_c[b * EDIM + 2 * t + 1] = h1;
}

// ---------------- zero the step-0 output slab ----------------
__global__ void zero_kernel(float4* __restrict__ p, int n4) {
    for (int i = blockIdx.x * blockDim.x + threadIdx.x; i < n4; i += gridDim.x * blockDim.x)
        p[i] = make_float4(0.f, 0.f, 0.f, 0.f);
}

// ================= HMMA GEMM (2-limb fp16, 3 products) =================
// C[M, N] = sum_p A_limb[pa[p]] @ B_limb[pb[p]]^T  (+bias)
// BM=128, BN=64, BK=64; 8 warps (4x2); warp tile 32x32.
__global__ void __launch_bounds__(256) hmma_kernel(const __half* __restrict__ Ab,
                                                   const __half* __restrict__ Bb,
                                                   size_t planeA, size_t planeB, int K,
                                                   const float* __restrict__ bias,
                                                   float* __restrict__ out,
                                                   int ldo, int Nvalid, int M) {
    __shared__ __align__(128) char sAraw[128 * 128];   // 128 rows x 128B
    __shared__ __align__(128) char sBraw[64 * 128];    // 64 rows x 128B
    uint32_t sA = smem_u32(sAraw);
    uint32_t sB = smem_u32(sBraw);

    int tid = threadIdx.x, lane = tid & 31, warp = tid >> 5;
    int warpM = warp >> 1, warpN = warp & 1;
    int bm0 = blockIdx.y * 128;
    int n0  = blockIdx.x * 64;

    int rAl[2], rBl[2];
#pragma unroll
    for (int mt = 0; mt < 2; mt++)
        rAl[mt] = warpM * 32 + mt * 16 + (lane & 7) + ((lane >> 3) & 1) * 8;
#pragma unroll
    for (int nt = 0; nt < 2; nt++)
        rBl[nt] = warpN * 32 + nt * 16 + (lane & 7) + (lane >> 4) * 8;
    int clA = lane >> 4;
    int clB = (lane >> 3) & 1;

    float acc[2][4][4];
#pragma unroll
    for (int a = 0; a < 2; a++)
#pragma unroll
        for (int b = 0; b < 4; b++)
#pragma unroll
            for (int c = 0; c < 4; c++) acc[a][b][c] = 0.f;

    const int KC = K >> 6;
    const int NC = 3 * KC;

    // per-thread load coords
    int liA_r[4], liA_c[4], liB_r[2], liB_c[2];
#pragma unroll
    for (int i = 0; i < 4; i++) { int li = i * 256 + tid; liA_r[i] = li >> 3; liA_c[i] = li & 7; }
#pragma unroll
    for (int i = 0; i < 2; i++) { int li = i * 256 + tid; liB_r[i] = li >> 3; liB_c[i] = li & 7; }

    uint4 pA[4], pB[2];
    // prefetch chunk 0 (limb 0 / limb 0)
#pragma unroll
    for (int i = 0; i < 4; i++) {
        int r = bm0 + liA_r[i]; r = r < M ? r : M - 1;
        pA[i] = *(const uint4*)(Ab + (size_t)r * K + liA_c[i] * 8);
    }
#pragma unroll
    for (int i = 0; i < 2; i++)
        pB[i] = *(const uint4*)(Bb + (size_t)(n0 + liB_r[i]) * K + liB_c[i] * 8);

#pragma unroll
    for (int i = 0; i < 4; i++)
        *(uint4*)(sAraw + liA_r[i] * 128 + ((liA_c[i] ^ (liA_r[i] & 7)) << 4)) = pA[i];
#pragma unroll
    for (int i = 0; i < 2; i++)
        *(uint4*)(sBraw + liB_r[i] * 128 + ((liB_c[i] ^ (liB_r[i] & 7)) << 4)) = pB[i];

    for (int kk = 0; kk < NC; kk++) {
        __syncthreads();

        if (kk + 1 < NC) {
            int p  = (kk + 1) / KC;
            int k0 = ((kk + 1) - p * KC) << 6;
            const __half* Ap = Ab + (size_t)g_pa[p] * planeA;
            const __half* Bp = Bb + (size_t)g_pb[p] * planeB;
#pragma unroll
            for (int i = 0; i < 4; i++) {
                int r = bm0 + liA_r[i]; r = r < M ? r : M - 1;
                pA[i] = *(const uint4*)(Ap + (size_t)r * K + k0 + liA_c[i] * 8);
            }
#pragma unroll
            for (int i = 0; i < 2; i++)
                pB[i] = *(const uint4*)(Bp + (size_t)(n0 + liB_r[i]) * K + k0 + liB_c[i] * 8);
        }

#pragma unroll
        for (int h = 0; h < 4; h++) {
            uint32_t af[2][4], bf[2][4];
#pragma unroll
            for (int mt = 0; mt < 2; mt++) {
                int r = rAl[mt];
                int c = (h * 2 + clA) ^ (r & 7);
                ldmatrix_x4(af[mt], sA + r * 128 + (c << 4));
            }
#pragma unroll
            for (int nt = 0; nt < 2; nt++) {
                int r = rBl[nt];
                int c = (h * 2 + clB) ^ (r & 7);
                ldmatrix_x4(bf[nt], sB + r * 128 + (c << 4));
            }
#pragma unroll
            for (int mt = 0; mt < 2; mt++)
#pragma unroll
                for (int nt = 0; nt < 2; nt++)
#pragma unroll
                    for (int j = 0; j < 2; j++)
                        mma16816(acc[mt][nt * 2 + j], af[mt], bf[nt][2 * j], bf[nt][2 * j + 1]);
        }

        __syncthreads();

        if (kk + 1 < NC) {
#pragma unroll
            for (int i = 0; i < 4; i++)
                *(uint4*)(sAraw + liA_r[i] * 128 + ((liA_c[i] ^ (liA_r[i] & 7)) << 4)) = pA[i];
#pragma unroll
            for (int i = 0; i < 2; i++)
                *(uint4*)(sBraw + liB_r[i] * 128 + ((liB_c[i] ^ (liB_r[i] & 7)) << 4)) = pB[i];
        }
    }

    // epilogue: bias + store
#pragma unroll
    for (int mt = 0; mt < 2; mt++) {
        int row0 = bm0 + warpM * 32 + mt * 16 + (lane >> 2);
#pragma unroll
        for (int n8 = 0; n8 < 4; n8++) {
            int col = n0 + warpN * 32 + n8 * 8 + (lane & 3) * 2;
            if (col < Nvalid) {
                float2 bv = *(const float2*)(bias + col);
                if (row0 < M) {
                    float2 v0 = make_float2(acc[mt][n8][0] + bv.x, acc[mt][n8][1] + bv.y);
                    *(float2*)(out + (size_t)row0 * ldo + col) = v0;
                }
                if (row0 + 8 < M) {
                    float2 v1 = make_float2(acc[mt][n8][2] + bv.x, acc[mt][n8][3] + bv.y);
                    *(float2*)(out + (size_t)(row0 + 8) * ldo + col) = v1;
                }
            }
        }
    }
}

// ---------------- per-step attention + z assembly (writes z limb planes) ----------------
__global__ void attn_kernel(const float* __restrict__ enc,
                            const float* __restrict__ emb,
                            const int* __restrict__ counts) {
    int b = blockIdx.x, t = threadIdx.x;
    int lane = t & 31, w = t >> 5;
    __shared__ float sh[EDIM];
    __shared__ float sc[CMAX];
    __shared__ float red[256];

    sh[t]       = g_h[b * EDIM + t];
    sh[t + 256] = g_h[b * EDIM + t + 256];
    __syncthreads();

    int cnt = counts[b], off = g_off[b];

    for (int c = w; c < cnt; c += 8) {
        const float* row = g_att + (size_t)(off + c) * EDIM;
        float s = 0.f;
#pragma unroll
        for (int j = 0; j < EDIM; j += 128) {
            float4 v = *(const float4*)(row + j + lane * 4);
            s += v.x * sh[j + lane * 4]     + v.y * sh[j + lane * 4 + 1]
               + v.z * sh[j + lane * 4 + 2] + v.w * sh[j + lane * 4 + 3];
        }
#pragma unroll
        for (int o = 16; o; o >>= 1) s += __shfl_xor_sync(0xFFFFFFFFu, s, o);
        if (lane == 0) sc[c] = s;
    }
    __syncthreads();

    float m = -3.4e38f;
    for (int c = t; c < cnt; c += 256) m = fmaxf(m, sc[c]);
    red[t] = m;
    __syncthreads();
    for (int d = 128; d; d >>= 1) {
        if (t < d) red[t] = fmaxf(red[t], red[t + d]);
        __syncthreads();
    }
    float mx = red[0];
    __syncthreads();

    float s = 0.f;
    for (int c = t; c < cnt; c += 256) {
        float e = expf(sc[c] - mx);
        sc[c] = e;
        s += e;
    }
    red[t] = s;
    __syncthreads();
    for (int d = 128; d; d >>= 1) {
        if (t < d) red[t] += red[t + d];
        __syncthreads();
    }
    float inv = 1.f / red[0];

    float2 acc = make_float2(0.f, 0.f);
    for (int c = 0; c < cnt; c++) {
        float wgt = sc[c];
        float2 v = *(const float2*)(enc + (size_t)(off + c) * EDIM + 2 * t);
        acc.x += wgt * v.x;
        acc.y += wgt * v.y;
    }
    size_t zr = (size_t)b * KZ;
    split2_store(acc.x * inv, g_z2, zr + 512 + 2 * t,     PLANE_Z);
    split2_store(acc.y * inv, g_z2, zr + 512 + 2 * t + 1, PLANE_Z);

    int tok = g_cur[b];
    split2_store(emb[(size_t)tok * EDIM + t],       g_z2, zr + t,       PLANE_Z);
    split2_store(emb[(size_t)tok * EDIM + t + 256], g_z2, zr + t + 256, PLANE_Z);
    split2_store(sh[t],       g_z2, zr + 1024 + t,       PLANE_Z);
    split2_store(sh[t + 256], g_z2, zr + 1024 + 256 + t, PLANE_Z);
}

// ---------------- LSTM pointwise (+ h limb split for logits GEMM) ----------------
__global__ void lstm_kernel() {
    int idx = blockIdx.x * blockDim.x + threadIdx.x;
    int b = idx >> 9, e = idx & 511;
    const float* g = g_gates + (size_t)b * GDIM;
    float gi = g[e], gf = g[512 + e], gg = g[1024 + e], go = g[1536 + e];
    float si = 1.f / (1.f + expf(-gi));
    float sf = 1.f / (1.f + expf(-gf));
    float so = 1.f / (1.f + expf(-go));
    float cn = sf * g_c[idx] + si * tanhf(gg);
    float hn = so * tanhf(cn);
    g_c[idx] = cn;
    g_h[idx] = hn;
    split2_store(hn, g_h2, (size_t)idx, PLANE_H);
}

// ---------------- argmax with first-index tie-break ----------------
__global__ void argmax_kernel(const float* __restrict__ logits) {
    int b = blockIdx.x, t = threadIdx.x;
    const float* row = logits + (size_t)b * VDIM;
    float best = -3.4e38f;
    int bi = VDIM;
    for (int j = t; j < VDIM; j += 256) {
        float v = row[j];
        if (v > best) { best = v; bi = j; }
    }
    __shared__ float sv[256];
    __shared__ int si[256];
    sv[t] = best; si[t] = bi;
    __syncthreads();
    for (int d = 128; d; d >>= 1) {
        if (t < d) {
            if (sv[t + d] > sv[t] || (sv[t + d] == sv[t] && si[t + d] < si[t])) {
                sv[t] = sv[t + d];
                si[t] = si[t + d];
            }
        }
        __syncthreads();
    }
    if (t == 0) g_cur[b] = si[0];
}

// ---------------- launch ----------------
extern "C" void kernel_launch(void* const* d_in, const int* in_sizes, int n_in,
                              void* d_out, int out_size) {
    const float* enc    = (const float*)d_in[0];
    const int*   tl     = (const int*)d_in[1];
    const int*   counts = (const int*)d_in[2];
    const float* emb    = (const float*)d_in[3];
    const float* attn_W = (const float*)d_in[4];
    const float* attn_b = (const float*)d_in[5];
    const float* W_ih   = (const float*)d_in[6];
    const float* W_hh   = (const float*)d_in[7];
    const float* b_ih   = (const float*)d_in[8];
    const float* b_hh   = (const float*)d_in[9];
    const float* proj_W = (const float*)d_in[10];
    const float* proj_b = (const float*)d_in[11];
    float* out = (float*)d_out;
    int n_paths = in_sizes[0] / EDIM;

    __half *pB2, *pW2, *pZ2, *pH2, *pE2, *pAW2;
    float *pGates, *pBg, *pAtt;
    cudaGetSymbolAddress((void**)&pB2, g_B2);
    cudaGetSymbolAddress((void**)&pW2, g_W2);
    cudaGetSymbolAddress((void**)&pZ2, g_z2);
    cudaGetSymbolAddress((void**)&pH2, g_h2);
    cudaGetSymbolAddress((void**)&pE2, g_E2);
    cudaGetSymbolAddress((void**)&pAW2, g_AW2);
    cudaGetSymbolAddress((void**)&pGates, g_gates);
    cudaGetSymbolAddress((void**)&pBg, g_bg);
    cudaGetSymbolAddress((void**)&pAtt, g_att);

    zero_kernel<<<2048, 256>>>((float4*)out, BATCH * VDIM / 4);
    init_meta_kernel<<<1, BATCH>>>(counts, tl);
    build_wg2_kernel<<<(GDIM * KZ + 255) / 256, 256>>>(W_ih, W_hh, b_ih, b_hh);
    {
        dim3 grid(VPAD / 32, EDIM / 32);
        prepB2_kernel<<<grid, dim3(32, 8)>>>(proj_W);
    }
    {
        dim3 grid(EDIM / 32, EDIM / 32);
        prepAW2_kernel<<<grid, dim3(32, 8)>>>(attn_W);
    }
    prepE2_kernel<<<(n_paths * EDIM + 255) / 256, 256>>>(enc, n_paths * EDIM);
    {   // att precompute on tensor cores
        dim3 grid(EDIM / 64, (n_paths + 127) / 128);
        hmma_kernel<<<grid, 256>>>(pE2, pAW2, PLANE_E, PLANE_AW, EDIM,
                                   attn_b, pAtt, EDIM, EDIM, n_paths);
    }
    init_h_kernel<<<BATCH, 256>>>(enc, counts);

    dim3 grid_gates(GDIM / 64, 2);
    dim3 grid_logits(VPAD / 64, 2);

    for (int t = 1; t < LSTEPS; t++) {
        attn_kernel<<<BATCH, 256>>>(enc, emb, counts);
        hmma_kernel<<<grid_gates, 256>>>(pZ2, pW2, PLANE_Z, PLANE_W, KZ,
                                         pBg, pGates, GDIM, GDIM, BATCH);
        lstm_kernel<<<BATCH * EDIM / 256, 256>>>();
        float* logits = out + (size_t)t * BATCH * VDIM;
        hmma_kernel<<<grid_logits, 256>>>(pH2, pB2, PLANE_H, PLANE_B, EDIM,
                                          proj_b, logits, VDIM, VDIM, BATCH);
        if (t < LSTEPS - 1) argmax_kernel<<<BATCH, 256>>>(logits);
    }
}

// round 6
// speedup vs baseline: 3.2452x; 1.9425x over previous
#include <cuda_runtime.h>
#include <cuda_fp16.h>
#include <math.h>
#include <stdint.h>

// ---------------- problem constants ----------------
#define BATCH 256
#define EDIM  512
#define VDIM  27000
#define VPAD  27008
#define LSTEPS 16
#define CMAX  200
#define KZ    1536
#define GDIM  2048

#define PLANE_B  ((size_t)VPAD * EDIM)
#define PLANE_W  ((size_t)GDIM * KZ)
#define PLANE_Z  ((size_t)BATCH * KZ)
#define PLANE_H  ((size_t)BATCH * EDIM)
#define PLANE_E  ((size_t)32768 * EDIM)
#define PLANE_AW ((size_t)EDIM * EDIM)

// ---------------- persistent device scratch ----------------
__device__ __align__(128) float g_att[32768 * EDIM];
__device__ __align__(128) float g_h[BATCH * EDIM];
__device__ __align__(128) float g_c[BATCH * EDIM];
__device__ __align__(128) float g_gatesP[3 * BATCH * GDIM];   // split-K partials
__device__ __align__(128) float g_bg[GDIM];
__device__ int   g_off[BATCH + 1];
__device__ unsigned long long g_amax[BATCH];                  // packed argmax keys
__device__ __align__(128) __half g_B2[2 * PLANE_B];
__device__ __align__(128) __half g_W2[2 * PLANE_W];
__device__ __align__(128) __half g_z2[2 * PLANE_Z];
__device__ __align__(128) __half g_h2[2 * PLANE_H];
__device__ __align__(128) __half g_E2[2 * PLANE_E];
__device__ __align__(128) __half g_AW2[2 * PLANE_AW];

// ---------------- helpers ----------------
__device__ __forceinline__ uint32_t smem_u32(const void* p) {
    uint32_t a;
    asm("{ .reg .u64 t; cvta.to.shared.u64 t, %1; cvt.u32.u64 %0, t; }" : "=r"(a) : "l"(p));
    return a;
}
__device__ __forceinline__ void split2_store(float v, __half* base, size_t off, size_t plane) {
    __half h = __float2half_rn(v);
    float r = v - __half2float(h);
    base[off]         = h;
    base[off + plane] = __float2half_rn(r);
}
__device__ __forceinline__ void ldmatrix_x4(uint32_t* r, uint32_t addr) {
    asm volatile("ldmatrix.sync.aligned.m8n8.x4.shared.b16 {%0,%1,%2,%3}, [%4];"
                 : "=r"(r[0]), "=r"(r[1]), "=r"(r[2]), "=r"(r[3]) : "r"(addr) : "memory");
}
__device__ __forceinline__ void mma16816(float* c, const uint32_t* a, uint32_t b0, uint32_t b1) {
    asm volatile(
        "mma.sync.aligned.m16n8k16.row.col.f32.f16.f16.f32 "
        "{%0,%1,%2,%3}, {%4,%5,%6,%7}, {%8,%9}, {%0,%1,%2,%3};"
        : "+f"(c[0]), "+f"(c[1]), "+f"(c[2]), "+f"(c[3])
        : "r"(a[0]), "r"(a[1]), "r"(a[2]), "r"(a[3]), "r"(b0), "r"(b1));
}
__device__ __forceinline__ void cp_async16(uint32_t dst, const void* src) {
    asm volatile("cp.async.cg.shared.global [%0], [%1], 16;" :: "r"(dst), "l"(src) : "memory");
}
#define CP_COMMIT() asm volatile("cp.async.commit_group;" ::: "memory")
#define CP_WAIT0()  asm volatile("cp.async.wait_group 0;" ::: "memory")
#define CP_WAIT1()  asm volatile("cp.async.wait_group 1;" ::: "memory")

__device__ __forceinline__ unsigned long long pack_key(float v, int col) {
    uint32_t u = __float_as_uint(v);
    u = (u & 0x80000000u) ? ~u : (u | 0x80000000u);
    return ((unsigned long long)u << 32) | (unsigned long long)(0x7FFFFFFFu - (uint32_t)col);
}

// ---------------- init: offsets prefix sum + initial tokens ----------------
__global__ void init_meta_kernel(const int* __restrict__ counts,
                                 const int* __restrict__ target_labels) {
    __shared__ int s[BATCH];
    int t = threadIdx.x;
    s[t] = counts[t];
    __syncthreads();
    for (int d = 1; d < BATCH; d <<= 1) {
        int v = (t >= d) ? s[t - d] : 0;
        __syncthreads();
        s[t] += v;
        __syncthreads();
    }
    g_off[t] = s[t] - counts[t];
    if (t == 0) g_off[BATCH] = s[BATCH - 1];
    // seed the packed key with the step-0 token (value part irrelevant)
    g_amax[t] = (unsigned long long)(0x7FFFFFFFu - (uint32_t)target_labels[t]);
}

// ---------------- prep kernels ----------------
__global__ void build_wg2_kernel(const float* __restrict__ W_ih,
                                 const float* __restrict__ W_hh,
                                 const float* __restrict__ b_ih,
                                 const float* __restrict__ b_hh) {
    int i = blockIdx.x * blockDim.x + threadIdx.x;
    if (i < GDIM * KZ) {
        int n = i / KZ, k = i % KZ;
        float v = (k < 1024) ? W_ih[(size_t)n * 1024 + k]
                             : W_hh[(size_t)n * 512 + (k - 1024)];
        split2_store(v, g_W2, (size_t)n * KZ + k, PLANE_W);
    }
    if (i < GDIM) g_bg[i] = b_ih[i] + b_hh[i];
}

__global__ void prepB2_kernel(const float* __restrict__ W) {
    __shared__ float tile[32][33];
    int n0 = blockIdx.x * 32, k0 = blockIdx.y * 32;
    int tx = threadIdx.x, ty = threadIdx.y;
#pragma unroll
    for (int i = 0; i < 4; i++) {
        int k = k0 + ty + i * 8, n = n0 + tx;
        tile[ty + i * 8][tx] = (n < VDIM) ? W[(size_t)k * VDIM + n] : 0.f;
    }
    __syncthreads();
#pragma unroll
    for (int i = 0; i < 4; i++)
        split2_store(tile[tx][ty + i * 8], g_B2,
                     (size_t)(n0 + ty + i * 8) * EDIM + k0 + tx, PLANE_B);
}

__global__ void prepAW2_kernel(const float* __restrict__ W) {
    __shared__ float tile[32][33];
    int n0 = blockIdx.x * 32, k0 = blockIdx.y * 32;
    int tx = threadIdx.x, ty = threadIdx.y;
#pragma unroll
    for (int i = 0; i < 4; i++)
        tile[ty + i * 8][tx] = W[(size_t)(k0 + ty + i * 8) * EDIM + n0 + tx];
    __syncthreads();
#pragma unroll
    for (int i = 0; i < 4; i++)
        split2_store(tile[tx][ty + i * 8], g_AW2,
                     (size_t)(n0 + ty + i * 8) * EDIM + k0 + tx, PLANE_AW);
}

__global__ void prepE2_kernel(const float* __restrict__ enc, int n_elem) {
    int i = blockIdx.x * blockDim.x + threadIdx.x;
    if (i < n_elem) split2_store(enc[i], g_E2, (size_t)i, PLANE_E);
}

__global__ void init_h_kernel(const float* __restrict__ enc,
                              const int* __restrict__ counts) {
    int b = blockIdx.x, t = threadIdx.x;
    int cnt = counts[b], off = g_off[b];
    float2 acc = make_float2(0.f, 0.f);
    for (int c = 0; c < cnt; c++) {
        float2 v = *(const float2*)(enc + (size_t)(off + c) * EDIM + 2 * t);
        acc.x += v.x; acc.y += v.y;
    }
    float inv = 1.f / (float)cnt;
    float h0 = acc.x * inv, h1 = acc.y * inv;
    g_h[b * EDIM + 2 * t]     = h0;  g_c[b * EDIM + 2 * t]     = h0;
    g_h[b * EDIM + 2 * t + 1] = h1;  g_c[b * EDIM + 2 * t + 1] = h1;
}

__global__ void zero_kernel(float4* __restrict__ p, int n4) {
    for (int i = blockIdx.x * blockDim.x + threadIdx.x; i < n4; i += gridDim.x * blockDim.x)
        p[i] = make_float4(0.f, 0.f, 0.f, 0.f);
}

// ================= HMMA GEMM, BM=256 x BN=64, cp.async 2-stage =================
// C[M,N] = sum_p A_limb[pa[p]] @ B_limb[pb[p]]^T (+bias), fp16 2-limb, 3 products.
// split=0: all 3 products in one pass (NC = 3*KC).
// split=1: product index = blockIdx.z, NC = KC, out += z*partStride, no bias.
#define ASTAGE (256 * 128)
#define BSTAGE (64 * 128)
#define SMEM_HMMA (2 * ASTAGE + 2 * BSTAGE + 128)

__global__ void __launch_bounds__(256) hmma256_kernel(
    const __half* __restrict__ Ab, const __half* __restrict__ Bb,
    size_t planeA, size_t planeB, int K,
    const float* __restrict__ bias, float* __restrict__ out,
    int ldo, int Nvalid, int M,
    unsigned long long* amax, int split, size_t partStride) {

    extern __shared__ char dyn_raw[];
    char* sAc = (char*)(((uintptr_t)dyn_raw + 127) & ~(uintptr_t)127);
    char* sBc = sAc + 2 * ASTAGE;
    uint32_t sAaddr = smem_u32(sAc);
    uint32_t sBaddr = smem_u32(sBc);

    int tid = threadIdx.x, lane = tid & 31, warp = tid >> 5;
    int warpM = warp >> 1, warpN = warp & 1;
    int bm0 = blockIdx.y * 256;
    int n0  = blockIdx.x * 64;
    int pz  = blockIdx.z;

    if (split) out += pz * partStride;

    const int KC = K >> 6;
    const int NC = split ? KC : 3 * KC;

    // ldmatrix fragment coords
    int rAl[4], rBl[2];
#pragma unroll
    for (int mt = 0; mt < 4; mt++)
        rAl[mt] = warpM * 64 + mt * 16 + (lane & 7) + ((lane >> 3) & 1) * 8;
#pragma unroll
    for (int nt = 0; nt < 2; nt++)
        rBl[nt] = warpN * 32 + nt * 16 + (lane & 7) + (lane >> 4) * 8;
    int clA = lane >> 4;
    int clB = (lane >> 3) & 1;

    // cp.async per-thread coords
    int liA_r[8], liA_c[8], liB_r[2], liB_c[2];
#pragma unroll
    for (int i = 0; i < 8; i++) { int li = i * 256 + tid; liA_r[i] = li >> 3; liA_c[i] = li & 7; }
#pragma unroll
    for (int i = 0; i < 2; i++) { int li = i * 256 + tid; liB_r[i] = li >> 3; liB_c[i] = li & 7; }

    auto issue_chunk = [&](int kk, int stg) {
        int p  = split ? pz : (kk / KC);
        int kb = (split ? kk : (kk - p * KC)) << 6;
        int pa = (p == 2) ? 1 : 0;      // schedule: hh, hm, mh
        int pb = (p == 1) ? 1 : 0;
        const __half* Ap = Ab + (size_t)pa * planeA + kb;
        const __half* Bp = Bb + (size_t)pb * planeB + kb;
        uint32_t dA = sAaddr + stg * ASTAGE;
        uint32_t dB = sBaddr + stg * BSTAGE;
#pragma unroll
        for (int i = 0; i < 8; i++) {
            int r = liA_r[i], c = liA_c[i];
            int gr = bm0 + r; gr = gr < M ? gr : M - 1;
            cp_async16(dA + r * 128 + ((c ^ (r & 7)) << 4),
                       Ap + (size_t)gr * K + c * 8);
        }
#pragma unroll
        for (int i = 0; i < 2; i++) {
            int r = liB_r[i], c = liB_c[i];
            cp_async16(dB + r * 128 + ((c ^ (r & 7)) << 4),
                       Bp + (size_t)(n0 + r) * K + c * 8);
        }
        CP_COMMIT();
    };

    float acc[4][4][4];
#pragma unroll
    for (int a = 0; a < 4; a++)
#pragma unroll
        for (int b = 0; b < 4; b++)
#pragma unroll
            for (int c = 0; c < 4; c++) acc[a][b][c] = 0.f;

    issue_chunk(0, 0);
    if (NC > 1) issue_chunk(1, 1);

    for (int kk = 0; kk < NC; kk++) {
        if (kk + 1 < NC) { CP_WAIT1(); } else { CP_WAIT0(); }
        __syncthreads();

        int stg = kk & 1;
        uint32_t sAb = sAaddr + stg * ASTAGE;
        uint32_t sBb = sBaddr + stg * BSTAGE;
#pragma unroll
        for (int h = 0; h < 4; h++) {
            uint32_t af[4][4], bf[2][4];
#pragma unroll
            for (int mt = 0; mt < 4; mt++) {
                int r = rAl[mt];
                int c = (h * 2 + clA) ^ (r & 7);
                ldmatrix_x4(af[mt], sAb + r * 128 + (c << 4));
            }
#pragma unroll
            for (int nt = 0; nt < 2; nt++) {
                int r = rBl[nt];
                int c = (h * 2 + clB) ^ (r & 7);
                ldmatrix_x4(bf[nt], sBb + r * 128 + (c << 4));
            }
#pragma unroll
            for (int mt = 0; mt < 4; mt++)
#pragma unroll
                for (int nt = 0; nt < 2; nt++)
#pragma unroll
                    for (int j = 0; j < 2; j++)
                        mma16816(acc[mt][nt * 2 + j], af[mt], bf[nt][2 * j], bf[nt][2 * j + 1]);
        }
        __syncthreads();
        if (kk + 2 < NC) issue_chunk(kk + 2, stg);
    }

    // ---- epilogue: bias + store (+ fused argmax) ----
#pragma unroll
    for (int mt = 0; mt < 4; mt++) {
        int row0 = bm0 + warpM * 64 + mt * 16 + (lane >> 2);
        unsigned long long k0 = 0ull, k1 = 0ull;
#pragma unroll
        for (int n8 = 0; n8 < 4; n8++) {
            int col = n0 + warpN * 32 + n8 * 8 + (lane & 3) * 2;
            if (col < Nvalid) {
                float bx = bias ? bias[col] : 0.f;
                float by = bias ? bias[col + 1] : 0.f;
                if (row0 < M) {
                    float v0 = acc[mt][n8][0] + bx, v1 = acc[mt][n8][1] + by;
                    *(float2*)(out + (size_t)row0 * ldo + col) = make_float2(v0, v1);
                    if (amax) {
                        unsigned long long ka = pack_key(v0, col);
                        unsigned long long kb2 = pack_key(v1, col + 1);
                        k0 = k0 > ka ? k0 : ka; k0 = k0 > kb2 ? k0 : kb2;
                    }
                }
                if (row0 + 8 < M) {
                    float v2 = acc[mt][n8][2] + bx, v3 = acc[mt][n8][3] + by;
                    *(float2*)(out + (size_t)(row0 + 8) * ldo + col) = make_float2(v2, v3);
                    if (amax) {
                        unsigned long long ka = pack_key(v2, col);
                        unsigned long long kb2 = pack_key(v3, col + 1);
                        k1 = k1 > ka ? k1 : ka; k1 = k1 > kb2 ? k1 : kb2;
                    }
                }
            }
        }
        if (amax) {
            // reduce across the 4 lanes owning this row
#pragma unroll
            for (int o = 1; o <= 2; o <<= 1) {
                unsigned long long t0 = __shfl_xor_sync(0xFFFFFFFFu, k0, o);
                unsigned long long t1 = __shfl_xor_sync(0xFFFFFFFFu, k1, o);
                k0 = k0 > t0 ? k0 : t0;
                k1 = k1 > t1 ? k1 : t1;
            }
            if ((lane & 3) == 0) {
                if (row0 < M && k0) atomicMax(&amax[row0], k0);
                if (row0 + 8 < M && k1) atomicMax(&amax[row0 + 8], k1);
            }
        }
    }
}

// ---------------- per-step attention + z assembly ----------------
__global__ void attn_kernel(const float* __restrict__ enc,
                            const float* __restrict__ emb,
                            const int* __restrict__ counts) {
    int b = blockIdx.x, t = threadIdx.x;
    int lane = t & 31, w = t >> 5;
    __shared__ float sh[EDIM];
    __shared__ float sc[CMAX];
    __shared__ float red[256];

    sh[t]       = g_h[b * EDIM + t];
    sh[t + 256] = g_h[b * EDIM + t + 256];
    __syncthreads();

    int cnt = counts[b], off = g_off[b];

    for (int c = w; c < cnt; c += 8) {
        const float* row = g_att + (size_t)(off + c) * EDIM;
        float s = 0.f;
#pragma unroll
        for (int j = 0; j < EDIM; j += 128) {
            float4 v = *(const float4*)(row + j + lane * 4);
            s += v.x * sh[j + lane * 4]     + v.y * sh[j + lane * 4 + 1]
               + v.z * sh[j + lane * 4 + 2] + v.w * sh[j + lane * 4 + 3];
        }
#pragma unroll
        for (int o = 16; o; o >>= 1) s += __shfl_xor_sync(0xFFFFFFFFu, s, o);
        if (lane == 0) sc[c] = s;
    }
    __syncthreads();

    float m = -3.4e38f;
    for (int c = t; c < cnt; c += 256) m = fmaxf(m, sc[c]);
    red[t] = m;
    __syncthreads();
    for (int d = 128; d; d >>= 1) {
        if (t < d) red[t] = fmaxf(red[t], red[t + d]);
        __syncthreads();
    }
    float mx = red[0];
    __syncthreads();

    float s = 0.f;
    for (int c = t; c < cnt; c += 256) {
        float e = expf(sc[c] - mx);
        sc[c] = e;
        s += e;
    }
    red[t] = s;
    __syncthreads();
    for (int d = 128; d; d >>= 1) {
        if (t < d) red[t] += red[t + d];
        __syncthreads();
    }
    float inv = 1.f / red[0];

    // attended: unroll x4 for MLP
    float2 a0 = make_float2(0.f, 0.f), a1 = a0, a2 = a0, a3 = a0;
    const float* ebase = enc + (size_t)off * EDIM + 2 * t;
    int c = 0;
    for (; c + 4 <= cnt; c += 4) {
        float w0 = sc[c], w1 = sc[c + 1], w2 = sc[c + 2], w3 = sc[c + 3];
        float2 v0 = *(const float2*)(ebase + (size_t)c * EDIM);
        float2 v1 = *(const float2*)(ebase + (size_t)(c + 1) * EDIM);
        float2 v2 = *(const float2*)(ebase + (size_t)(c + 2) * EDIM);
        float2 v3 = *(const float2*)(ebase + (size_t)(c + 3) * EDIM);
        a0.x += w0 * v0.x; a0.y += w0 * v0.y;
        a1.x += w1 * v1.x; a1.y += w1 * v1.y;
        a2.x += w2 * v2.x; a2.y += w2 * v2.y;
        a3.x += w3 * v3.x; a3.y += w3 * v3.y;
    }
    for (; c < cnt; c++) {
        float w0 = sc[c];
        float2 v0 = *(const float2*)(ebase + (size_t)c * EDIM);
        a0.x += w0 * v0.x; a0.y += w0 * v0.y;
    }
    float ax = ((a0.x + a1.x) + (a2.x + a3.x)) * inv;
    float ay = ((a0.y + a1.y) + (a2.y + a3.y)) * inv;

    size_t zr = (size_t)b * KZ;
    split2_store(ax, g_z2, zr + 512 + 2 * t,     PLANE_Z);
    split2_store(ay, g_z2, zr + 512 + 2 * t + 1, PLANE_Z);

    int tok = 0x7FFFFFFF - (int)(uint32_t)(g_amax[b] & 0xFFFFFFFFull);
    split2_store(emb[(size_t)tok * EDIM + t],       g_z2, zr + t,       PLANE_Z);
    split2_store(emb[(size_t)tok * EDIM + t + 256], g_z2, zr + t + 256, PLANE_Z);
    split2_store(sh[t],       g_z2, zr + 1024 + t,       PLANE_Z);
    split2_store(sh[t + 256], g_z2, zr + 1024 + 256 + t, PLANE_Z);
}

// ---------------- LSTM pointwise: sum split-K partials + bias, reset amax ----------------
__global__ void lstm_kernel() {
    int idx = blockIdx.x * blockDim.x + threadIdx.x;   // BATCH*EDIM
    if (idx < BATCH) g_amax[idx] = 0ull;               // reset keys for this step's logits
    int b = idx >> 9, e = idx & 511;
    const float* g0 = g_gatesP + (size_t)b * GDIM;
    const float* g1 = g0 + (size_t)BATCH * GDIM;
    const float* g2 = g1 + (size_t)BATCH * GDIM;
    float gi = g0[e]        + g1[e]        + g2[e]        + g_bg[e];
    float gf = g0[512 + e]  + g1[512 + e]  + g2[512 + e]  + g_bg[512 + e];
    float gg = g0[1024 + e] + g1[1024 + e] + g2[1024 + e] + g_bg[1024 + e];
    float go = g0[1536 + e] + g1[1536 + e] + g2[1536 + e] + g_bg[1536 + e];
    float si = 1.f / (1.f + expf(-gi));
    float sf = 1.f / (1.f + expf(-gf));
    float so = 1.f / (1.f + expf(-go));
    float cn = sf * g_c[idx] + si * tanhf(gg);
    float hn = so * tanhf(cn);
    g_c[idx] = cn;
    g_h[idx] = hn;
    split2_store(hn, g_h2, (size_t)idx, PLANE_H);
}

// ---------------- launch ----------------
extern "C" void kernel_launch(void* const* d_in, const int* in_sizes, int n_in,
                              void* d_out, int out_size) {
    const float* enc    = (const float*)d_in[0];
    const int*   tl     = (const int*)d_in[1];
    const int*   counts = (const int*)d_in[2];
    const float* emb    = (const float*)d_in[3];
    const float* attn_W = (const float*)d_in[4];
    const float* attn_b = (const float*)d_in[5];
    const float* W_ih   = (const float*)d_in[6];
    const float* W_hh   = (const float*)d_in[7];
    const float* b_ih   = (const float*)d_in[8];
    const float* b_hh   = (const float*)d_in[9];
    const float* proj_W = (const float*)d_in[10];
    const float* proj_b = (const float*)d_in[11];
    float* out = (float*)d_out;
    int n_paths = in_sizes[0] / EDIM;

    __half *pB2, *pW2, *pZ2, *pH2, *pE2, *pAW2;
    float *pGatesP, *pAtt;
    unsigned long long* pAmax;
    cudaGetSymbolAddress((void**)&pB2, g_B2);
    cudaGetSymbolAddress((void**)&pW2, g_W2);
    cudaGetSymbolAddress((void**)&pZ2, g_z2);
    cudaGetSymbolAddress((void**)&pH2, g_h2);
    cudaGetSymbolAddress((void**)&pE2, g_E2);
    cudaGetSymbolAddress((void**)&pAW2, g_AW2);
    cudaGetSymbolAddress((void**)&pGatesP, g_gatesP);
    cudaGetSymbolAddress((void**)&pAtt, g_att);
    cudaGetSymbolAddress((void**)&pAmax, g_amax);

    cudaFuncSetAttribute(hmma256_kernel,
                         cudaFuncAttributeMaxDynamicSharedMemorySize, SMEM_HMMA);

    zero_kernel<<<2048, 256>>>((float4*)out, BATCH * VDIM / 4);
    init_meta_kernel<<<1, BATCH>>>(counts, tl);
    build_wg2_kernel<<<(GDIM * KZ + 255) / 256, 256>>>(W_ih, W_hh, b_ih, b_hh);
    {
        dim3 grid(VPAD / 32, EDIM / 32);
        prepB2_kernel<<<grid, dim3(32, 8)>>>(proj_W);
    }
    {
        dim3 grid(EDIM / 32, EDIM / 32);
        prepAW2_kernel<<<grid, dim3(32, 8)>>>(attn_W);
    }
    prepE2_kernel<<<(n_paths * EDIM + 255) / 256, 256>>>(enc, n_paths * EDIM);
    {   // att precompute on tensor cores
        dim3 grid(EDIM / 64, (n_paths + 255) / 256, 1);
        hmma256_kernel<<<grid, 256, SMEM_HMMA>>>(pE2, pAW2, PLANE_E, PLANE_AW, EDIM,
                                                 attn_b, pAtt, EDIM, EDIM, n_paths,
                                                 nullptr, 0, 0);
    }
    init_h_kernel<<<BATCH, 256>>>(enc, counts);

    dim3 grid_gates(GDIM / 64, 1, 3);
    dim3 grid_logits(VPAD / 64, 1, 1);

    for (int t = 1; t < LSTEPS; t++) {
        attn_kernel<<<BATCH, 256>>>(enc, emb, counts);
        hmma256_kernel<<<grid_gates, 256, SMEM_HMMA>>>(pZ2, pW2, PLANE_Z, PLANE_W, KZ,
                                                       nullptr, pGatesP, GDIM, GDIM, BATCH,
                                                       nullptr, 1, (size_t)BATCH * GDIM);
        lstm_kernel<<<BATCH * EDIM / 256, 256>>>();
        float* logits = out + (size_t)t * BATCH * VDIM;
        hmma256_kernel<<<grid_logits, 256, SMEM_HMMA>>>(pH2, pB2, PLANE_H, PLANE_B, EDIM,
                                                        proj_b, logits, VDIM, VDIM, BATCH,
                                                        (t < LSTEPS - 1) ? pAmax : nullptr,
                                                        0, 0);
    }
}

// round 7
// speedup vs baseline: 3.4887x; 1.0750x over previous
#include <cuda_runtime.h>
#include <cuda_fp16.h>
#include <math.h>
#include <stdint.h>

// ---------------- problem constants ----------------
#define BATCH 256
#define EDIM  512
#define VDIM  27000
#define VPAD  27008
#define LSTEPS 16
#define CMAX  200
#define KZ    1536
#define GDIM  2048

#define PLANE_B  ((size_t)VPAD * EDIM)
#define PLANE_W  ((size_t)GDIM * KZ)
#define PLANE_Z  ((size_t)BATCH * KZ)
#define PLANE_H  ((size_t)BATCH * EDIM)
#define PLANE_E  ((size_t)32768 * EDIM)
#define PLANE_AW ((size_t)EDIM * EDIM)

// ---------------- persistent device scratch ----------------
__device__ __align__(128) float g_att[32768 * EDIM];
__device__ __align__(128) float g_h[BATCH * EDIM];
__device__ __align__(128) float g_c[BATCH * EDIM];
__device__ __align__(128) float g_gatesP[3 * BATCH * GDIM];
__device__ __align__(128) float g_bg[GDIM];
__device__ int   g_off[BATCH + 1];
__device__ unsigned long long g_amax[BATCH];
__device__ __align__(128) __half g_B2[2 * PLANE_B];
__device__ __align__(128) __half g_W2[2 * PLANE_W];
__device__ __align__(128) __half g_z2[2 * PLANE_Z];
__device__ __align__(128) __half g_h2[2 * PLANE_H];
__device__ __align__(128) __half g_E2[2 * PLANE_E];
__device__ __align__(128) __half g_AW2[2 * PLANE_AW];

// ---------------- helpers ----------------
__device__ __forceinline__ uint32_t smem_u32(const void* p) {
    uint32_t a;
    asm("{ .reg .u64 t; cvta.to.shared.u64 t, %1; cvt.u32.u64 %0, t; }" : "=r"(a) : "l"(p));
    return a;
}
__device__ __forceinline__ void split2_store(float v, __half* base, size_t off, size_t plane) {
    __half h = __float2half_rn(v);
    float r = v - __half2float(h);
    base[off]         = h;
    base[off + plane] = __float2half_rn(r);
}
__device__ __forceinline__ void ldmatrix_x4(uint32_t* r, uint32_t addr) {
    asm volatile("ldmatrix.sync.aligned.m8n8.x4.shared.b16 {%0,%1,%2,%3}, [%4];"
                 : "=r"(r[0]), "=r"(r[1]), "=r"(r[2]), "=r"(r[3]) : "r"(addr) : "memory");
}
__device__ __forceinline__ void mma16816(float* c, const uint32_t* a, uint32_t b0, uint32_t b1) {
    asm volatile(
        "mma.sync.aligned.m16n8k16.row.col.f32.f16.f16.f32 "
        "{%0,%1,%2,%3}, {%4,%5,%6,%7}, {%8,%9}, {%0,%1,%2,%3};"
        : "+f"(c[0]), "+f"(c[1]), "+f"(c[2]), "+f"(c[3])
        : "r"(a[0]), "r"(a[1]), "r"(a[2]), "r"(a[3]), "r"(b0), "r"(b1));
}
__device__ __forceinline__ void cp_async16(uint32_t dst, const void* src) {
    asm volatile("cp.async.cg.shared.global [%0], [%1], 16;" :: "r"(dst), "l"(src) : "memory");
}
#define CP_COMMIT() asm volatile("cp.async.commit_group;" ::: "memory")
#define CP_WAIT0()  asm volatile("cp.async.wait_group 0;" ::: "memory")
#define CP_WAIT1()  asm volatile("cp.async.wait_group 1;" ::: "memory")

__device__ __forceinline__ unsigned long long pack_key(float v, int col) {
    uint32_t u = __float_as_uint(v);
    u = (u & 0x80000000u) ? ~u : (u | 0x80000000u);
    return ((unsigned long long)u << 32) | (unsigned long long)(0x7FFFFFFFu - (uint32_t)col);
}

// ---------------- init: offsets prefix sum + initial tokens ----------------
__global__ void init_meta_kernel(const int* __restrict__ counts,
                                 const int* __restrict__ target_labels) {
    __shared__ int s[BATCH];
    int t = threadIdx.x;
    s[t] = counts[t];
    __syncthreads();
    for (int d = 1; d < BATCH; d <<= 1) {
        int v = (t >= d) ? s[t - d] : 0;
        __syncthreads();
        s[t] += v;
        __syncthreads();
    }
    g_off[t] = s[t] - counts[t];
    if (t == 0) g_off[BATCH] = s[BATCH - 1];
    g_amax[t] = (unsigned long long)(0x7FFFFFFFu - (uint32_t)target_labels[t]);
}

// ---------------- prep kernels ----------------
__global__ void build_wg2_kernel(const float* __restrict__ W_ih,
                                 const float* __restrict__ W_hh,
                                 const float* __restrict__ b_ih,
                                 const float* __restrict__ b_hh) {
    int i = blockIdx.x * blockDim.x + threadIdx.x;
    if (i < GDIM * KZ) {
        int n = i / KZ, k = i % KZ;
        float v = (k < 1024) ? W_ih[(size_t)n * 1024 + k]
                             : W_hh[(size_t)n * 512 + (k - 1024)];
        split2_store(v, g_W2, (size_t)n * KZ + k, PLANE_W);
    }
    if (i < GDIM) g_bg[i] = b_ih[i] + b_hh[i];
}

__global__ void prepB2_kernel(const float* __restrict__ W) {
    __shared__ float tile[32][33];
    int n0 = blockIdx.x * 32, k0 = blockIdx.y * 32;
    int tx = threadIdx.x, ty = threadIdx.y;
#pragma unroll
    for (int i = 0; i < 4; i++) {
        int k = k0 + ty + i * 8, n = n0 + tx;
        tile[ty + i * 8][tx] = (n < VDIM) ? W[(size_t)k * VDIM + n] : 0.f;
    }
    __syncthreads();
#pragma unroll
    for (int i = 0; i < 4; i++)
        split2_store(tile[tx][ty + i * 8], g_B2,
                     (size_t)(n0 + ty + i * 8) * EDIM + k0 + tx, PLANE_B);
}

__global__ void prepAW2_kernel(const float* __restrict__ W) {
    __shared__ float tile[32][33];
    int n0 = blockIdx.x * 32, k0 = blockIdx.y * 32;
    int tx = threadIdx.x, ty = threadIdx.y;
#pragma unroll
    for (int i = 0; i < 4; i++)
        tile[ty + i * 8][tx] = W[(size_t)(k0 + ty + i * 8) * EDIM + n0 + tx];
    __syncthreads();
#pragma unroll
    for (int i = 0; i < 4; i++)
        split2_store(tile[tx][ty + i * 8], g_AW2,
                     (size_t)(n0 + ty + i * 8) * EDIM + k0 + tx, PLANE_AW);
}

__global__ void prepE2_kernel(const float* __restrict__ enc, int n_elem) {
    int i = blockIdx.x * blockDim.x + threadIdx.x;
    if (i < n_elem) split2_store(enc[i], g_E2, (size_t)i, PLANE_E);
}

__global__ void init_h_kernel(const float* __restrict__ enc,
                              const int* __restrict__ counts) {
    int b = blockIdx.x, t = threadIdx.x;
    int cnt = counts[b], off = g_off[b];
    float2 acc = make_float2(0.f, 0.f);
    for (int c = 0; c < cnt; c++) {
        float2 v = *(const float2*)(enc + (size_t)(off + c) * EDIM + 2 * t);
        acc.x += v.x; acc.y += v.y;
    }
    float inv = 1.f / (float)cnt;
    float h0 = acc.x * inv, h1 = acc.y * inv;
    g_h[b * EDIM + 2 * t]     = h0;  g_c[b * EDIM + 2 * t]     = h0;
    g_h[b * EDIM + 2 * t + 1] = h1;  g_c[b * EDIM + 2 * t + 1] = h1;
}

__global__ void zero_kernel(float4* __restrict__ p, int n4) {
    for (int i = blockIdx.x * blockDim.x + threadIdx.x; i < n4; i += gridDim.x * blockDim.x)
        p[i] = make_float4(0.f, 0.f, 0.f, 0.f);
}

// ================= fused HMMA GEMM =================
// C[M,N] = A_h@B_h^T + A_h@B_m^T + A_m@B_h^T  (fp16 2-limb, 3 products)
// Fused chunk schedule: F = 2*KC chunks of 64 K-columns.
//   f < KC : A-limb hi, products vs B-hi AND B-mi (2 MMAs sets per chunk)
//   f >= KC: A-limb mi, product vs B-hi only
// Each stage holds A tile (32KB) + B-hi tile (8KB) + B-mi tile (8KB).
// 3-stage cp.async pipeline, one __syncthreads per chunk.
// Split-K: block handles f = blockIdx.z, +gridDim.z, ... ; partials when gridDim.z>1.
#define ASTAGE (256 * 128)
#define BSTAGE (64 * 128)
#define STAGE_BYTES (ASTAGE + 2 * BSTAGE)
#define SMEM_HMMA (3 * STAGE_BYTES + 128)

__global__ void __launch_bounds__(256) hmma_fused_kernel(
    const __half* __restrict__ Ab, const __half* __restrict__ Bb,
    size_t planeA, size_t planeB, int K,
    const float* __restrict__ bias, float* __restrict__ out,
    int ldo, int Nvalid, int M,
    unsigned long long* amax, size_t partStride) {

    extern __shared__ char dyn_raw[];
    char* sbase = (char*)(((uintptr_t)dyn_raw + 127) & ~(uintptr_t)127);
    uint32_t sb = smem_u32(sbase);

    int tid = threadIdx.x, lane = tid & 31, warp = tid >> 5;
    int warpM = warp >> 1, warpN = warp & 1;
    int bm0 = blockIdx.y * 256;
    int n0  = blockIdx.x * 64;
    int z   = blockIdx.z, zs = gridDim.z;

    if (zs > 1) out += (size_t)z * partStride;

    const int KC = K >> 6;
    const int F  = 2 * KC;
    const int NCb = (F - z + zs - 1) / zs;

    int rAl[4], rBl[2];
#pragma unroll
    for (int mt = 0; mt < 4; mt++)
        rAl[mt] = warpM * 64 + mt * 16 + (lane & 7) + ((lane >> 3) & 1) * 8;
#pragma unroll
    for (int nt = 0; nt < 2; nt++)
        rBl[nt] = warpN * 32 + nt * 16 + (lane & 7) + (lane >> 4) * 8;
    int clA = lane >> 4;
    int clB = (lane >> 3) & 1;

    int liA_r[8], liA_c[8], liB_r[2], liB_c[2];
#pragma unroll
    for (int i = 0; i < 8; i++) { int li = i * 256 + tid; liA_r[i] = li >> 3; liA_c[i] = li & 7; }
#pragma unroll
    for (int i = 0; i < 2; i++) { int li = i * 256 + tid; liB_r[i] = li >> 3; liB_c[i] = li & 7; }

    auto issue_chunk = [&](int f, int stg) {
        int aL = (f < KC) ? 0 : 1;
        int kb = ((f < KC) ? f : f - KC) << 6;
        const __half* Ap = Ab + (size_t)aL * planeA + kb;
        uint32_t dA  = sb + stg * STAGE_BYTES;
        uint32_t dBh = dA + ASTAGE;
        uint32_t dBm = dBh + BSTAGE;
#pragma unroll
        for (int i = 0; i < 8; i++) {
            int r = liA_r[i], c = liA_c[i];
            int gr = bm0 + r; gr = gr < M ? gr : M - 1;
            cp_async16(dA + r * 128 + ((c ^ (r & 7)) << 4),
                       Ap + (size_t)gr * K + c * 8);
        }
        const __half* Bph = Bb + kb;
#pragma unroll
        for (int i = 0; i < 2; i++) {
            int r = liB_r[i], c = liB_c[i];
            cp_async16(dBh + r * 128 + ((c ^ (r & 7)) << 4),
                       Bph + (size_t)(n0 + r) * K + c * 8);
        }
        if (f < KC) {
            const __half* Bpm = Bb + planeB + kb;
#pragma unroll
            for (int i = 0; i < 2; i++) {
                int r = liB_r[i], c = liB_c[i];
                cp_async16(dBm + r * 128 + ((c ^ (r & 7)) << 4),
                           Bpm + (size_t)(n0 + r) * K + c * 8);
            }
        }
        CP_COMMIT();
    };

    float acc[4][4][4];
#pragma unroll
    for (int a = 0; a < 4; a++)
#pragma unroll
        for (int b = 0; b < 4; b++)
#pragma unroll
            for (int c = 0; c < 4; c++) acc[a][b][c] = 0.f;

    issue_chunk(z, 0);
    if (NCb > 1) issue_chunk(z + zs, 1);

    for (int i = 0; i < NCb; i++) {
        int f = z + i * zs;
        if (i + 1 < NCb) { CP_WAIT1(); } else { CP_WAIT0(); }
        __syncthreads();
        if (i + 2 < NCb) issue_chunk(z + (i + 2) * zs, (i + 2) % 3);

        int stg = i % 3;
        uint32_t sAb  = sb + stg * STAGE_BYTES;
        uint32_t sBhb = sAb + ASTAGE;
        uint32_t sBmb = sBhb + BSTAGE;
        bool two = (f < KC);
#pragma unroll
        for (int h = 0; h < 4; h++) {
            uint32_t af[4][4], bfh[2][4];
#pragma unroll
            for (int mt = 0; mt < 4; mt++) {
                int r = rAl[mt];
                int c = (h * 2 + clA) ^ (r & 7);
                ldmatrix_x4(af[mt], sAb + r * 128 + (c << 4));
            }
#pragma unroll
            for (int nt = 0; nt < 2; nt++) {
                int r = rBl[nt];
                int c = (h * 2 + clB) ^ (r & 7);
                ldmatrix_x4(bfh[nt], sBhb + r * 128 + (c << 4));
            }
#pragma unroll
            for (int mt = 0; mt < 4; mt++)
#pragma unroll
                for (int nt = 0; nt < 2; nt++)
#pragma unroll
                    for (int j = 0; j < 2; j++)
                        mma16816(acc[mt][nt * 2 + j], af[mt], bfh[nt][2 * j], bfh[nt][2 * j + 1]);
            if (two) {
                uint32_t bfm[2][4];
#pragma unroll
                for (int nt = 0; nt < 2; nt++) {
                    int r = rBl[nt];
                    int c = (h * 2 + clB) ^ (r & 7);
                    ldmatrix_x4(bfm[nt], sBmb + r * 128 + (c << 4));
                }
#pragma unroll
                for (int mt = 0; mt < 4; mt++)
#pragma unroll
                    for (int nt = 0; nt < 2; nt++)
#pragma unroll
                        for (int j = 0; j < 2; j++)
                            mma16816(acc[mt][nt * 2 + j], af[mt], bfm[nt][2 * j], bfm[nt][2 * j + 1]);
            }
        }
    }

    // ---- epilogue: bias + store (+ fused argmax) ----
#pragma unroll
    for (int mt = 0; mt < 4; mt++) {
        int row0 = bm0 + warpM * 64 + mt * 16 + (lane >> 2);
        unsigned long long k0 = 0ull, k1 = 0ull;
#pragma unroll
        for (int n8 = 0; n8 < 4; n8++) {
            int col = n0 + warpN * 32 + n8 * 8 + (lane & 3) * 2;
            if (col < Nvalid) {
                float bx = bias ? bias[col] : 0.f;
                float by = bias ? bias[col + 1] : 0.f;
                if (row0 < M) {
                    float v0 = acc[mt][n8][0] + bx, v1 = acc[mt][n8][1] + by;
                    *(float2*)(out + (size_t)row0 * ldo + col) = make_float2(v0, v1);
                    if (amax) {
                        unsigned long long ka = pack_key(v0, col);
                        unsigned long long kb2 = pack_key(v1, col + 1);
                        k0 = k0 > ka ? k0 : ka; k0 = k0 > kb2 ? k0 : kb2;
                    }
                }
                if (row0 + 8 < M) {
                    float v2 = acc[mt][n8][2] + bx, v3 = acc[mt][n8][3] + by;
                    *(float2*)(out + (size_t)(row0 + 8) * ldo + col) = make_float2(v2, v3);
                    if (amax) {
                        unsigned long long ka = pack_key(v2, col);
                        unsigned long long kb2 = pack_key(v3, col + 1);
                        k1 = k1 > ka ? k1 : ka; k1 = k1 > kb2 ? k1 : kb2;
                    }
                }
            }
        }
        if (amax) {
#pragma unroll
            for (int o = 1; o <= 2; o <<= 1) {
                unsigned long long t0 = __shfl_xor_sync(0xFFFFFFFFu, k0, o);
                unsigned long long t1 = __shfl_xor_sync(0xFFFFFFFFu, k1, o);
                k0 = k0 > t0 ? k0 : t0;
                k1 = k1 > t1 ? k1 : t1;
            }
            if ((lane & 3) == 0) {
                if (row0 < M && k0) atomicMax(&amax[row0], k0);
                if (row0 + 8 < M && k1) atomicMax(&amax[row0 + 8], k1);
            }
        }
    }
}

// ---------------- per-step attention + z assembly (512 threads) ----------------
__global__ void __launch_bounds__(512) attn_kernel(const float* __restrict__ enc,
                                                   const float* __restrict__ emb,
                                                   const int* __restrict__ counts) {
    int b = blockIdx.x, t = threadIdx.x;
    int lane = t & 31, w = t >> 5;           // 16 warps
    __shared__ float sh[EDIM];
    __shared__ float sc[CMAX];
    __shared__ float red[512];

    sh[t] = g_h[b * EDIM + t];
    __syncthreads();

    int cnt = counts[b], off = g_off[b];

    // scores: one context per warp, 16-warp round-robin
    for (int c = w; c < cnt; c += 16) {
        const float* row = g_att + (size_t)(off + c) * EDIM;
        float s = 0.f;
#pragma unroll
        for (int j = 0; j < EDIM; j += 128) {
            float4 v = *(const float4*)(row + j + lane * 4);
            s += v.x * sh[j + lane * 4]     + v.y * sh[j + lane * 4 + 1]
               + v.z * sh[j + lane * 4 + 2] + v.w * sh[j + lane * 4 + 3];
        }
#pragma unroll
        for (int o = 16; o; o >>= 1) s += __shfl_xor_sync(0xFFFFFFFFu, s, o);
        if (lane == 0) sc[c] = s;
    }
    __syncthreads();

    // softmax
    float m = -3.4e38f;
    for (int c = t; c < cnt; c += 512) m = fmaxf(m, sc[c]);
    red[t] = m;
    __syncthreads();
    for (int d = 256; d; d >>= 1) {
        if (t < d) red[t] = fmaxf(red[t], red[t + d]);
        __syncthreads();
    }
    float mx = red[0];
    __syncthreads();

    float s = 0.f;
    for (int c = t; c < cnt; c += 512) {
        float e = expf(sc[c] - mx);
        sc[c] = e;
        s += e;
    }
    red[t] = s;
    __syncthreads();
    for (int d = 256; d; d >>= 1) {
        if (t < d) red[t] += red[t + d];
        __syncthreads();
    }
    float inv = 1.f / red[0];

    // attended: each thread owns 1 column, 8-way unroll
    float a0 = 0.f, a1 = 0.f, a2 = 0.f, a3 = 0.f, a4 = 0.f, a5 = 0.f, a6 = 0.f, a7 = 0.f;
    const float* ebase = enc + (size_t)off * EDIM + t;
    int c = 0;
    for (; c + 8 <= cnt; c += 8) {
        a0 += sc[c + 0] * ebase[(size_t)(c + 0) * EDIM];
        a1 += sc[c + 1] * ebase[(size_t)(c + 1) * EDIM];
        a2 += sc[c + 2] * ebase[(size_t)(c + 2) * EDIM];
        a3 += sc[c + 3] * ebase[(size_t)(c + 3) * EDIM];
        a4 += sc[c + 4] * ebase[(size_t)(c + 4) * EDIM];
        a5 += sc[c + 5] * ebase[(size_t)(c + 5) * EDIM];
        a6 += sc[c + 6] * ebase[(size_t)(c + 6) * EDIM];
        a7 += sc[c + 7] * ebase[(size_t)(c + 7) * EDIM];
    }
    for (; c < cnt; c++) a0 += sc[c] * ebase[(size_t)c * EDIM];
    float ax = (((a0 + a1) + (a2 + a3)) + ((a4 + a5) + (a6 + a7))) * inv;

    size_t zr = (size_t)b * KZ;
    split2_store(ax, g_z2, zr + 512 + t, PLANE_Z);

    int tok = 0x7FFFFFFF - (int)(uint32_t)(g_amax[b] & 0xFFFFFFFFull);
    split2_store(emb[(size_t)tok * EDIM + t], g_z2, zr + t, PLANE_Z);
    split2_store(sh[t], g_z2, zr + 1024 + t, PLANE_Z);
}

// ---------------- LSTM pointwise: sum split-K partials + bias, reset amax ----------------
__global__ void lstm_kernel() {
    int idx = blockIdx.x * blockDim.x + threadIdx.x;
    if (idx < BATCH) g_amax[idx] = 0ull;
    int b = idx >> 9, e = idx & 511;
    const float* g0 = g_gatesP + (size_t)b * GDIM;
    const float* g1 = g0 + (size_t)BATCH * GDIM;
    const float* g2 = g1 + (size_t)BATCH * GDIM;
    float gi = g0[e]        + g1[e]        + g2[e]        + g_bg[e];
    float gf = g0[512 + e]  + g1[512 + e]  + g2[512 + e]  + g_bg[512 + e];
    float gg = g0[1024 + e] + g1[1024 + e] + g2[1024 + e] + g_bg[1024 + e];
    float go = g0[1536 + e] + g1[1536 + e] + g2[1536 + e] + g_bg[1536 + e];
    float si = 1.f / (1.f + expf(-gi));
    float sf = 1.f / (1.f + expf(-gf));
    float so = 1.f / (1.f + expf(-go));
    float cn = sf * g_c[idx] + si * tanhf(gg);
    float hn = so * tanhf(cn);
    g_c[idx] = cn;
    g_h[idx] = hn;
    split2_store(hn, g_h2, (size_t)idx, PLANE_H);
}

// ---------------- launch ----------------
extern "C" void kernel_launch(void* const* d_in, const int* in_sizes, int n_in,
                              void* d_out, int out_size) {
    const float* enc    = (const float*)d_in[0];
    const int*   tl     = (const int*)d_in[1];
    const int*   counts = (const int*)d_in[2];
    const float* emb    = (const float*)d_in[3];
    const float* attn_W = (const float*)d_in[4];
    const float* attn_b = (const float*)d_in[5];
    const float* W_ih   = (const float*)d_in[6];
    const float* W_hh   = (const float*)d_in[7];
    const float* b_ih   = (const float*)d_in[8];
    const float* b_hh   = (const float*)d_in[9];
    const float* proj_W = (const float*)d_in[10];
    const float* proj_b = (const float*)d_in[11];
    float* out = (float*)d_out;
    int n_paths = in_sizes[0] / EDIM;

    __half *pB2, *pW2, *pZ2, *pH2, *pE2, *pAW2;
    float *pGatesP, *pAtt;
    unsigned long long* pAmax;
    cudaGetSymbolAddress((void**)&pB2, g_B2);
    cudaGetSymbolAddress((void**)&pW2, g_W2);
    cudaGetSymbolAddress((void**)&pZ2, g_z2);
    cudaGetSymbolAddress((void**)&pH2, g_h2);
    cudaGetSymbolAddress((void**)&pE2, g_E2);
    cudaGetSymbolAddress((void**)&pAW2, g_AW2);
    cudaGetSymbolAddress((void**)&pGatesP, g_gatesP);
    cudaGetSymbolAddress((void**)&pAtt, g_att);
    cudaGetSymbolAddress((void**)&pAmax, g_amax);

    cudaFuncSetAttribute(hmma_fused_kernel,
                         cudaFuncAttributeMaxDynamicSharedMemorySize, SMEM_HMMA);

    zero_kernel<<<2048, 256>>>((float4*)out, BATCH * VDIM / 4);
    init_meta_kernel<<<1, BATCH>>>(counts, tl);
    build_wg2_kernel<<<(GDIM * KZ + 255) / 256, 256>>>(W_ih, W_hh, b_ih, b_hh);
    {
        dim3 grid(VPAD / 32, EDIM / 32);
        prepB2_kernel<<<grid, dim3(32, 8)>>>(proj_W);
    }
    {
        dim3 grid(EDIM / 32, EDIM / 32);
        prepAW2_kernel<<<grid, dim3(32, 8)>>>(attn_W);
    }
    prepE2_kernel<<<(n_paths * EDIM + 255) / 256, 256>>>(enc, n_paths * EDIM);
    {   // att precompute on tensor cores
        dim3 grid(EDIM / 64, (n_paths + 255) / 256, 1);
        hmma_fused_kernel<<<grid, 256, SMEM_HMMA>>>(pE2, pAW2, PLANE_E, PLANE_AW, EDIM,
                                                    attn_b, pAtt, EDIM, EDIM, n_paths,
                                                    nullptr, 0);
    }
    init_h_kernel<<<BATCH, 256>>>(enc, counts);

    dim3 grid_gates(GDIM / 64, 1, 3);
    dim3 grid_logits(VPAD / 64, 1, 1);

    for (int t = 1; t < LSTEPS; t++) {
        attn_kernel<<<BATCH, 512>>>(enc, emb, counts);
        hmma_fused_kernel<<<grid_gates, 256, SMEM_HMMA>>>(pZ2, pW2, PLANE_Z, PLANE_W, KZ,
                                                          nullptr, pGatesP, GDIM, GDIM, BATCH,
                                                          nullptr, (size_t)BATCH * GDIM);
        lstm_kernel<<<BATCH * EDIM / 256, 256>>>();
        float* logits = out + (size_t)t * BATCH * VDIM;
        hmma_fused_kernel<<<grid_logits, 256, SMEM_HMMA>>>(pH2, pB2, PLANE_H, PLANE_B, EDIM,
                                                           proj_b, logits, VDIM, VDIM, BATCH,
                                                           (t < LSTEPS - 1) ? pAmax : nullptr,
                                                           0);
    }
}

// round 8
// speedup vs baseline: 4.1134x; 1.1791x over previous
#include <cuda_runtime.h>
#include <cuda_fp16.h>
#include <math.h>
#include <stdint.h>

// ---------------- problem constants ----------------
#define BATCH 256
#define EDIM  512
#define VDIM  27000
#define VPAD  27008
#define LSTEPS 16
#define CMAX  200
#define KZ    1536
#define GDIM  2048

#define PLANE_B  ((size_t)VPAD * EDIM)
#define PLANE_W  ((size_t)GDIM * KZ)
#define PLANE_Z  ((size_t)BATCH * KZ)
#define PLANE_H  ((size_t)BATCH * EDIM)
#define PLANE_E  ((size_t)32768 * EDIM)
#define PLANE_AW ((size_t)EDIM * EDIM)

// ---------------- persistent device scratch ----------------
__device__ __align__(128) float g_att[32768 * EDIM];
__device__ __align__(128) float g_h[BATCH * EDIM];
__device__ __align__(128) float g_c[BATCH * EDIM];
__device__ __align__(128) float g_gatesP[3 * BATCH * GDIM];
__device__ __align__(128) float g_bg[GDIM];
__device__ int   g_off[BATCH + 1];
__device__ unsigned long long g_amax[BATCH];
__device__ __align__(128) __half g_B2[2 * PLANE_B];
__device__ __align__(128) __half g_W2[2 * PLANE_W];
__device__ __align__(128) __half g_z2[2 * PLANE_Z];
__device__ __align__(128) __half g_h2[2 * PLANE_H];
__device__ __align__(128) __half g_E2[2 * PLANE_E];
__device__ __align__(128) __half g_AW2[2 * PLANE_AW];

// ---------------- helpers ----------------
__device__ __forceinline__ uint32_t smem_u32(const void* p) {
    uint32_t a;
    asm("{ .reg .u64 t; cvta.to.shared.u64 t, %1; cvt.u32.u64 %0, t; }" : "=r"(a) : "l"(p));
    return a;
}
__device__ __forceinline__ void split2_store(float v, __half* base, size_t off, size_t plane) {
    __half h = __float2half_rn(v);
    float r = v - __half2float(h);
    base[off]         = h;
    base[off + plane] = __float2half_rn(r);
}
__device__ __forceinline__ void ldmatrix_x4(uint32_t* r, uint32_t addr) {
    asm volatile("ldmatrix.sync.aligned.m8n8.x4.shared.b16 {%0,%1,%2,%3}, [%4];"
                 : "=r"(r[0]), "=r"(r[1]), "=r"(r[2]), "=r"(r[3]) : "r"(addr) : "memory");
}
__device__ __forceinline__ void mma16816(float* c, const uint32_t* a, uint32_t b0, uint32_t b1) {
    asm volatile(
        "mma.sync.aligned.m16n8k16.row.col.f32.f16.f16.f32 "
        "{%0,%1,%2,%3}, {%4,%5,%6,%7}, {%8,%9}, {%0,%1,%2,%3};"
        : "+f"(c[0]), "+f"(c[1]), "+f"(c[2]), "+f"(c[3])
        : "r"(a[0]), "r"(a[1]), "r"(a[2]), "r"(a[3]), "r"(b0), "r"(b1));
}
__device__ __forceinline__ void cp_async16(uint32_t dst, const void* src) {
    asm volatile("cp.async.cg.shared.global [%0], [%1], 16;" :: "r"(dst), "l"(src) : "memory");
}
#define CP_COMMIT() asm volatile("cp.async.commit_group;" ::: "memory")
#define CP_WAIT0()  asm volatile("cp.async.wait_group 0;" ::: "memory")
#define CP_WAIT1()  asm volatile("cp.async.wait_group 1;" ::: "memory")

__device__ __forceinline__ unsigned long long pack_key(float v, int col) {
    uint32_t u = __float_as_uint(v);
    u = (u & 0x80000000u) ? ~u : (u | 0x80000000u);
    return ((unsigned long long)u << 32) | (unsigned long long)(0x7FFFFFFFu - (uint32_t)col);
}

// ---------------- init: offsets prefix sum + initial tokens ----------------
__global__ void init_meta_kernel(const int* __restrict__ counts,
                                 const int* __restrict__ target_labels) {
    __shared__ int s[BATCH];
    int t = threadIdx.x;
    s[t] = counts[t];
    __syncthreads();
    for (int d = 1; d < BATCH; d <<= 1) {
        int v = (t >= d) ? s[t - d] : 0;
        __syncthreads();
        s[t] += v;
        __syncthreads();
    }
    g_off[t] = s[t] - counts[t];
    if (t == 0) g_off[BATCH] = s[BATCH - 1];
    g_amax[t] = (unsigned long long)(0x7FFFFFFFu - (uint32_t)target_labels[t]);
}

// ---------------- prep kernels ----------------
__global__ void build_wg2_kernel(const float* __restrict__ W_ih,
                                 const float* __restrict__ W_hh,
                                 const float* __restrict__ b_ih,
                                 const float* __restrict__ b_hh) {
    int i = blockIdx.x * blockDim.x + threadIdx.x;
    if (i < GDIM * KZ) {
        int n = i / KZ, k = i % KZ;
        float v = (k < 1024) ? W_ih[(size_t)n * 1024 + k]
                             : W_hh[(size_t)n * 512 + (k - 1024)];
        split2_store(v, g_W2, (size_t)n * KZ + k, PLANE_W);
    }
    if (i < GDIM) g_bg[i] = b_ih[i] + b_hh[i];
}

__global__ void prepB2_kernel(const float* __restrict__ W) {
    __shared__ float tile[32][33];
    int n0 = blockIdx.x * 32, k0 = blockIdx.y * 32;
    int tx = threadIdx.x, ty = threadIdx.y;
#pragma unroll
    for (int i = 0; i < 4; i++) {
        int k = k0 + ty + i * 8, n = n0 + tx;
        tile[ty + i * 8][tx] = (n < VDIM) ? W[(size_t)k * VDIM + n] : 0.f;
    }
    __syncthreads();
#pragma unroll
    for (int i = 0; i < 4; i++)
        split2_store(tile[tx][ty + i * 8], g_B2,
                     (size_t)(n0 + ty + i * 8) * EDIM + k0 + tx, PLANE_B);
}

__global__ void prepAW2_kernel(const float* __restrict__ W) {
    __shared__ float tile[32][33];
    int n0 = blockIdx.x * 32, k0 = blockIdx.y * 32;
    int tx = threadIdx.x, ty = threadIdx.y;
#pragma unroll
    for (int i = 0; i < 4; i++)
        tile[ty + i * 8][tx] = W[(size_t)(k0 + ty + i * 8) * EDIM + n0 + tx];
    __syncthreads();
#pragma unroll
    for (int i = 0; i < 4; i++)
        split2_store(tile[tx][ty + i * 8], g_AW2,
                     (size_t)(n0 + ty + i * 8) * EDIM + k0 + tx, PLANE_AW);
}

__global__ void prepE2_kernel(const float* __restrict__ enc, int n_elem) {
    int i = blockIdx.x * blockDim.x + threadIdx.x;
    if (i < n_elem) split2_store(enc[i], g_E2, (size_t)i, PLANE_E);
}

__global__ void init_h_kernel(const float* __restrict__ enc,
                              const int* __restrict__ counts) {
    int b = blockIdx.x, t = threadIdx.x;
    int cnt = counts[b], off = g_off[b];
    float2 acc = make_float2(0.f, 0.f);
    for (int c = 0; c < cnt; c++) {
        float2 v = *(const float2*)(enc + (size_t)(off + c) * EDIM + 2 * t);
        acc.x += v.x; acc.y += v.y;
    }
    float inv = 1.f / (float)cnt;
    float h0 = acc.x * inv, h1 = acc.y * inv;
    int i0 = b * EDIM + 2 * t, i1 = i0 + 1;
    g_h[i0] = h0;  g_c[i0] = h0;
    g_h[i1] = h1;  g_c[i1] = h1;
    // h limbs for the first logits GEMM
    split2_store(h0, g_h2, (size_t)i0, PLANE_H);
    split2_store(h1, g_h2, (size_t)i1, PLANE_H);
    // z h-slot limbs for the first gates GEMM
    size_t zr = (size_t)b * KZ + 1024;
    split2_store(h0, g_z2, zr + 2 * t,     PLANE_Z);
    split2_store(h1, g_z2, zr + 2 * t + 1, PLANE_Z);
}

__global__ void zero_kernel(float4* __restrict__ p, int n4) {
    for (int i = blockIdx.x * blockDim.x + threadIdx.x; i < n4; i += gridDim.x * blockDim.x)
        p[i] = make_float4(0.f, 0.f, 0.f, 0.f);
}

// ---------------- attn block body (runs as extra blocks of the fused kernel) ----------------
__device__ void attn_block_body(const float* __restrict__ enc,
                                const int* __restrict__ counts,
                                int b, char* dyn) {
    int t = threadIdx.x;
    int lane = t & 31, w = t >> 5;     // 8 warps
    float* sh  = (float*)dyn;          // 512
    float* sc  = sh + EDIM;            // CMAX
    float* red = sc + CMAX;            // 256

    sh[t]       = g_h[b * EDIM + t];
    sh[t + 256] = g_h[b * EDIM + t + 256];
    __syncthreads();

    int cnt = counts[b], off = g_off[b];

    for (int c = w; c < cnt; c += 8) {
        const float* row = g_att + (size_t)(off + c) * EDIM;
        float s = 0.f;
#pragma unroll
        for (int j = 0; j < EDIM; j += 128) {
            float4 v = *(const float4*)(row + j + lane * 4);
            s += v.x * sh[j + lane * 4]     + v.y * sh[j + lane * 4 + 1]
               + v.z * sh[j + lane * 4 + 2] + v.w * sh[j + lane * 4 + 3];
        }
#pragma unroll
        for (int o = 16; o; o >>= 1) s += __shfl_xor_sync(0xFFFFFFFFu, s, o);
        if (lane == 0) sc[c] = s;
    }
    __syncthreads();

    float m = -3.4e38f;
    for (int c = t; c < cnt; c += 256) m = fmaxf(m, sc[c]);
    red[t] = m;
    __syncthreads();
    for (int d = 128; d; d >>= 1) {
        if (t < d) red[t] = fmaxf(red[t], red[t + d]);
        __syncthreads();
    }
    float mx = red[0];
    __syncthreads();

    float s = 0.f;
    for (int c = t; c < cnt; c += 256) {
        float e = expf(sc[c] - mx);
        sc[c] = e;
        s += e;
    }
    red[t] = s;
    __syncthreads();
    for (int d = 128; d; d >>= 1) {
        if (t < d) red[t] += red[t + d];
        __syncthreads();
    }
    float inv = 1.f / red[0];

    // attended: 2 cols/thread, 4-way unroll
    float2 a0 = make_float2(0.f, 0.f), a1 = a0, a2 = a0, a3 = a0;
    const float* ebase = enc + (size_t)off * EDIM + 2 * t;
    int c = 0;
    for (; c + 4 <= cnt; c += 4) {
        float w0 = sc[c], w1 = sc[c + 1], w2 = sc[c + 2], w3 = sc[c + 3];
        float2 v0 = *(const float2*)(ebase + (size_t)c * EDIM);
        float2 v1 = *(const float2*)(ebase + (size_t)(c + 1) * EDIM);
        float2 v2 = *(const float2*)(ebase + (size_t)(c + 2) * EDIM);
        float2 v3 = *(const float2*)(ebase + (size_t)(c + 3) * EDIM);
        a0.x += w0 * v0.x; a0.y += w0 * v0.y;
        a1.x += w1 * v1.x; a1.y += w1 * v1.y;
        a2.x += w2 * v2.x; a2.y += w2 * v2.y;
        a3.x += w3 * v3.x; a3.y += w3 * v3.y;
    }
    for (; c < cnt; c++) {
        float w0 = sc[c];
        float2 v0 = *(const float2*)(ebase + (size_t)c * EDIM);
        a0.x += w0 * v0.x; a0.y += w0 * v0.y;
    }
    float ax = ((a0.x + a1.x) + (a2.x + a3.x)) * inv;
    float ay = ((a0.y + a1.y) + (a2.y + a3.y)) * inv;

    size_t zr = (size_t)b * KZ;
    split2_store(ax, g_z2, zr + 512 + 2 * t,     PLANE_Z);
    split2_store(ay, g_z2, zr + 512 + 2 * t + 1, PLANE_Z);
}

// ================= fused HMMA GEMM + optional attn blocks =================
// Blocks [0, nLog): C[M,N] = A_h@B_h^T + A_h@B_m^T + A_m@B_h^T (fp16 2-limb)
// Blocks [nLog, nLog+nAttn) (z==0): attention for batch row (blockIdx.x - nLog).
// 2-stage cp.async; stage = A(32KB) + B_h(8KB) + B_m(8KB) = 48KB; 2 blocks/SM.
#define ASTAGE (256 * 128)
#define BSTAGE (64 * 128)
#define STAGE_BYTES (ASTAGE + 2 * BSTAGE)
#define SMEM_HMMA (2 * STAGE_BYTES + 128)

__global__ void __launch_bounds__(256, 2) hmma_fused_kernel(
    const __half* __restrict__ Ab, const __half* __restrict__ Bb,
    size_t planeA, size_t planeB, int K,
    const float* __restrict__ bias, float* __restrict__ out,
    int ldo, int Nvalid, int M,
    unsigned long long* amax, size_t partStride, int nLog,
    const float* __restrict__ enc, const int* __restrict__ counts) {

    extern __shared__ char dyn_raw[];
    if ((int)blockIdx.x >= nLog) {
        if (blockIdx.z == 0)
            attn_block_body(enc, counts, blockIdx.x - nLog, dyn_raw);
        return;
    }

    char* sbase = (char*)(((uintptr_t)dyn_raw + 127) & ~(uintptr_t)127);
    uint32_t sb = smem_u32(sbase);

    int tid = threadIdx.x, lane = tid & 31, warp = tid >> 5;
    int warpM = warp >> 1, warpN = warp & 1;
    int bm0 = blockIdx.y * 256;
    int n0  = blockIdx.x * 64;
    int z   = blockIdx.z, zs = gridDim.z;

    if (zs > 1) out += (size_t)z * partStride;

    const int KC = K >> 6;
    const int F  = 2 * KC;
    const int NCb = (F - z + zs - 1) / zs;

    int rAl[4], rBl[2];
#pragma unroll
    for (int mt = 0; mt < 4; mt++)
        rAl[mt] = warpM * 64 + mt * 16 + (lane & 7) + ((lane >> 3) & 1) * 8;
#pragma unroll
    for (int nt = 0; nt < 2; nt++)
        rBl[nt] = warpN * 32 + nt * 16 + (lane & 7) + (lane >> 4) * 8;
    int clA = lane >> 4;
    int clB = (lane >> 3) & 1;

    int liA_r[8], liA_c[8], liB_r[2], liB_c[2];
#pragma unroll
    for (int i = 0; i < 8; i++) { int li = i * 256 + tid; liA_r[i] = li >> 3; liA_c[i] = li & 7; }
#pragma unroll
    for (int i = 0; i < 2; i++) { int li = i * 256 + tid; liB_r[i] = li >> 3; liB_c[i] = li & 7; }

    auto issue_chunk = [&](int f, int stg) {
        int aL = (f < KC) ? 0 : 1;
        int kb = ((f < KC) ? f : f - KC) << 6;
        const __half* Ap = Ab + (size_t)aL * planeA + kb;
        uint32_t dA  = sb + stg * STAGE_BYTES;
        uint32_t dBh = dA + ASTAGE;
        uint32_t dBm = dBh + BSTAGE;
#pragma unroll
        for (int i = 0; i < 8; i++) {
            int r = liA_r[i], c = liA_c[i];
            int gr = bm0 + r; gr = gr < M ? gr : M - 1;
            cp_async16(dA + r * 128 + ((c ^ (r & 7)) << 4),
                       Ap + (size_t)gr * K + c * 8);
        }
        const __half* Bph = Bb + kb;
#pragma unroll
        for (int i = 0; i < 2; i++) {
            int r = liB_r[i], c = liB_c[i];
            cp_async16(dBh + r * 128 + ((c ^ (r & 7)) << 4),
                       Bph + (size_t)(n0 + r) * K + c * 8);
        }
        if (f < KC) {
            const __half* Bpm = Bb + planeB + kb;
#pragma unroll
            for (int i = 0; i < 2; i++) {
                int r = liB_r[i], c = liB_c[i];
                cp_async16(dBm + r * 128 + ((c ^ (r & 7)) << 4),
                           Bpm + (size_t)(n0 + r) * K + c * 8);
            }
        }
        CP_COMMIT();
    };

    float acc[4][4][4];
#pragma unroll
    for (int a = 0; a < 4; a++)
#pragma unroll
        for (int b = 0; b < 4; b++)
#pragma unroll
            for (int c = 0; c < 4; c++) acc[a][b][c] = 0.f;

    issue_chunk(z, 0);
    if (NCb > 1) issue_chunk(z + zs, 1);

    for (int i = 0; i < NCb; i++) {
        int f = z + i * zs;
        if (i + 1 < NCb) { CP_WAIT1(); } else { CP_WAIT0(); }
        __syncthreads();

        int stg = i & 1;
        uint32_t sAb  = sb + stg * STAGE_BYTES;
        uint32_t sBhb = sAb + ASTAGE;
        uint32_t sBmb = sBhb + BSTAGE;
        bool two = (f < KC);
#pragma unroll
        for (int h = 0; h < 4; h++) {
            uint32_t af[4][4], bfh[2][4];
#pragma unroll
            for (int mt = 0; mt < 4; mt++) {
                int r = rAl[mt];
                int c = (h * 2 + clA) ^ (r & 7);
                ldmatrix_x4(af[mt], sAb + r * 128 + (c << 4));
            }
#pragma unroll
            for (int nt = 0; nt < 2; nt++) {
                int r = rBl[nt];
                int c = (h * 2 + clB) ^ (r & 7);
                ldmatrix_x4(bfh[nt], sBhb + r * 128 + (c << 4));
            }
#pragma unroll
            for (int mt = 0; mt < 4; mt++)
#pragma unroll
                for (int nt = 0; nt < 2; nt++)
#pragma unroll
                    for (int j = 0; j < 2; j++)
                        mma16816(acc[mt][nt * 2 + j], af[mt], bfh[nt][2 * j], bfh[nt][2 * j + 1]);
            if (two) {
                uint32_t bfm[2][4];
#pragma unroll
                for (int nt = 0; nt < 2; nt++) {
                    int r = rBl[nt];
                    int c = (h * 2 + clB) ^ (r & 7);
                    ldmatrix_x4(bfm[nt], sBmb + r * 128 + (c << 4));
                }
#pragma unroll
                for (int mt = 0; mt < 4; mt++)
#pragma unroll
                    for (int nt = 0; nt < 2; nt++)
#pragma unroll
                        for (int j = 0; j < 2; j++)
                            mma16816(acc[mt][nt * 2 + j], af[mt], bfm[nt][2 * j], bfm[nt][2 * j + 1]);
            }
        }
        __syncthreads();
        if (i + 2 < NCb) issue_chunk(z + (i + 2) * zs, stg);
    }

    // ---- epilogue: bias + store (+ fused argmax) ----
#pragma unroll
    for (int mt = 0; mt < 4; mt++) {
        int row0 = bm0 + warpM * 64 + mt * 16 + (lane >> 2);
        unsigned long long k0 = 0ull, k1 = 0ull;
#pragma unroll
        for (int n8 = 0; n8 < 4; n8++) {
            int col = n0 + warpN * 32 + n8 * 8 + (lane & 3) * 2;
            if (col < Nvalid) {
                float bx = bias ? bias[col] : 0.f;
                float by = bias ? bias[col + 1] : 0.f;
                if (row0 < M) {
                    float v0 = acc[mt][n8][0] + bx, v1 = acc[mt][n8][1] + by;
                    *(float2*)(out + (size_t)row0 * ldo + col) = make_float2(v0, v1);
                    if (amax) {
                        unsigned long long ka = pack_key(v0, col);
                        unsigned long long kb2 = pack_key(v1, col + 1);
                        k0 = k0 > ka ? k0 : ka; k0 = k0 > kb2 ? k0 : kb2;
                    }
                }
                if (row0 + 8 < M) {
                    float v2 = acc[mt][n8][2] + bx, v3 = acc[mt][n8][3] + by;
                    *(float2*)(out + (size_t)(row0 + 8) * ldo + col) = make_float2(v2, v3);
                    if (amax) {
                        unsigned long long ka = pack_key(v2, col);
                        unsigned long long kb2 = pack_key(v3, col + 1);
                        k1 = k1 > ka ? k1 : ka; k1 = k1 > kb2 ? k1 : kb2;
                    }
                }
            }
        }
        if (amax) {
#pragma unroll
            for (int o = 1; o <= 2; o <<= 1) {
                unsigned long long t0 = __shfl_xor_sync(0xFFFFFFFFu, k0, o);
                unsigned long long t1 = __shfl_xor_sync(0xFFFFFFFFu, k1, o);
                k0 = k0 > t0 ? k0 : t0;
                k1 = k1 > t1 ? k1 : t1;
            }
            if ((lane & 3) == 0) {
                if (row0 < M && k0) atomicMax(&amax[row0], k0);
                if (row0 + 8 < M && k1) atomicMax(&amax[row0 + 8], k1);
            }
        }
    }
}

// ---------------- emb lookup -> z slot [0,512) limbs (needs finalized amax) ----------------
__global__ void emb_z_kernel(const float* __restrict__ emb) {
    int b = blockIdx.x, t = threadIdx.x;   // 256 threads
    int tok = 0x7FFFFFFF - (int)(uint32_t)(g_amax[b] & 0xFFFFFFFFull);
    size_t zr = (size_t)b * KZ;
    split2_store(emb[(size_t)tok * EDIM + t],       g_z2, zr + t,       PLANE_Z);
    split2_store(emb[(size_t)tok * EDIM + t + 256], g_z2, zr + t + 256, PLANE_Z);
}

// ---------------- LSTM: sum split-K partials + bias; write h, h-limbs, z-h limbs; reset amax ----------------
__global__ void lstm_kernel() {
    int idx = blockIdx.x * blockDim.x + threadIdx.x;
    if (idx < BATCH) g_amax[idx] = 0ull;
    int b = idx >> 9, e = idx & 511;
    const float* g0 = g_gatesP + (size_t)b * GDIM;
    const float* g1 = g0 + (size_t)BATCH * GDIM;
    const float* g2 = g1 + (size_t)BATCH * GDIM;
    float gi = g0[e]        + g1[e]        + g2[e]        + g_bg[e];
    float gf = g0[512 + e]  + g1[512 + e]  + g2[512 + e]  + g_bg[512 + e];
    float gg = g0[1024 + e] + g1[1024 + e] + g2[1024 + e] + g_bg[1024 + e];
    float go = g0[1536 + e] + g1[1536 + e] + g2[1536 + e] + g_bg[1536 + e];
    float si = 1.f / (1.f + expf(-gi));
    float sf = 1.f / (1.f + expf(-gf));
    float so = 1.f / (1.f + expf(-go));
    float cn = sf * g_c[idx] + si * tanhf(gg);
    float hn = so * tanhf(cn);
    g_c[idx] = cn;
    g_h[idx] = hn;
    split2_store(hn, g_h2, (size_t)idx, PLANE_H);
    split2_store(hn, g_z2, (size_t)b * KZ + 1024 + e, PLANE_Z);
}

// ---------------- launch ----------------
extern "C" void kernel_launch(void* const* d_in, const int* in_sizes, int n_in,
                              void* d_out, int out_size) {
    const float* enc    = (const float*)d_in[0];
    const int*   tl     = (const int*)d_in[1];
    const int*   counts = (const int*)d_in[2];
    const float* emb    = (const float*)d_in[3];
    const float* attn_W = (const float*)d_in[4];
    const float* attn_b = (const float*)d_in[5];
    const float* W_ih   = (const float*)d_in[6];
    const float* W_hh   = (const float*)d_in[7];
    const float* b_ih   = (const float*)d_in[8];
    const float* b_hh   = (const float*)d_in[9];
    const float* proj_W = (const float*)d_in[10];
    const float* proj_b = (const float*)d_in[11];
    float* out = (float*)d_out;
    int n_paths = in_sizes[0] / EDIM;

    __half *pB2, *pW2, *pZ2, *pH2, *pE2, *pAW2;
    float *pGatesP, *pAtt;
    unsigned long long* pAmax;
    cudaGetSymbolAddress((void**)&pB2, g_B2);
    cudaGetSymbolAddress((void**)&pW2, g_W2);
    cudaGetSymbolAddress((void**)&pZ2, g_z2);
    cudaGetSymbolAddress((void**)&pH2, g_h2);
    cudaGetSymbolAddress((void**)&pE2, g_E2);
    cudaGetSymbolAddress((void**)&pAW2, g_AW2);
    cudaGetSymbolAddress((void**)&pGatesP, g_gatesP);
    cudaGetSymbolAddress((void**)&pAtt, g_att);
    cudaGetSymbolAddress((void**)&pAmax, g_amax);

    cudaFuncSetAttribute(hmma_fused_kernel,
                         cudaFuncAttributeMaxDynamicSharedMemorySize, SMEM_HMMA);

    zero_kernel<<<2048, 256>>>((float4*)out, BATCH * VDIM / 4);
    init_meta_kernel<<<1, BATCH>>>(counts, tl);
    build_wg2_kernel<<<(GDIM * KZ + 255) / 256, 256>>>(W_ih, W_hh, b_ih, b_hh);
    {
        dim3 grid(VPAD / 32, EDIM / 32);
        prepB2_kernel<<<grid, dim3(32, 8)>>>(proj_W);
    }
    {
        dim3 grid(EDIM / 32, EDIM / 32);
        prepAW2_kernel<<<grid, dim3(32, 8)>>>(attn_W);
    }
    prepE2_kernel<<<(n_paths * EDIM + 255) / 256, 256>>>(enc, n_paths * EDIM);
    {   // att precompute on tensor cores
        dim3 grid(EDIM / 64, (n_paths + 255) / 256, 1);
        hmma_fused_kernel<<<grid, 256, SMEM_HMMA>>>(pE2, pAW2, PLANE_E, PLANE_AW, EDIM,
                                                    attn_b, pAtt, EDIM, EDIM, n_paths,
                                                    nullptr, 0, EDIM / 64, nullptr, nullptr);
    }
    init_h_kernel<<<BATCH, 256>>>(enc, counts);

    const int NLOG = VPAD / 64;                 // 422
    dim3 grid_gates(GDIM / 64, 1, 3);
    dim3 grid_fused(NLOG + BATCH, 1, 1);
    dim3 grid_attn_only(BATCH, 1, 1);

    // Pipeline per t: [attn(t) || logits(t-1)] -> emb_z(t) -> gates(t) -> lstm(t)
    for (int t = 1; t < LSTEPS; t++) {
        if (t == 1) {
            hmma_fused_kernel<<<grid_attn_only, 256, SMEM_HMMA>>>(
                pH2, pB2, PLANE_H, PLANE_B, EDIM, proj_b, out, VDIM, VDIM, BATCH,
                nullptr, 0, 0, enc, counts);
        } else {
            float* logits = out + (size_t)(t - 1) * BATCH * VDIM;
            hmma_fused_kernel<<<grid_fused, 256, SMEM_HMMA>>>(
                pH2, pB2, PLANE_H, PLANE_B, EDIM, proj_b, logits, VDIM, VDIM, BATCH,
                pAmax, 0, NLOG, enc, counts);
        }
        emb_z_kernel<<<BATCH, 256>>>(emb);
        hmma_fused_kernel<<<grid_gates, 256, SMEM_HMMA>>>(
            pZ2, pW2, PLANE_Z, PLANE_W, KZ, nullptr, pGatesP, GDIM, GDIM, BATCH,
            nullptr, (size_t)BATCH * GDIM, GDIM / 64, nullptr, nullptr);
        lstm_kernel<<<BATCH * EDIM / 256, 256>>>();
    }
    {   // final logits (step 15), no argmax needed
        float* logits = out + (size_t)(LSTEPS - 1) * BATCH * VDIM;
        dim3 grid_last(NLOG, 1, 1);
        hmma_fused_kernel<<<grid_last, 256, SMEM_HMMA>>>(
            pH2, pB2, PLANE_H, PLANE_B, EDIM, proj_b, logits, VDIM, VDIM, BATCH,
            nullptr, 0, NLOG, nullptr, nullptr);
    }
}

// round 13
// speedup vs baseline: 5.0576x; 1.2296x over previous
#include <cuda_runtime.h>
#include <cuda_fp16.h>
#include <math.h>
#include <stdint.h>

// ---------------- problem constants ----------------
#define BATCH 256
#define EDIM  512
#define VDIM  27000
#define VPAD  27008
#define LSTEPS 16
#define CMAX  200
#define KZ    1536
#define GDIM  2048

#define PLANE_B  ((size_t)VPAD * EDIM)
#define PLANE_W  ((size_t)GDIM * KZ)
#define PLANE_Z  ((size_t)BATCH * KZ)
#define PLANE_H  ((size_t)BATCH * EDIM)
#define PLANE_AW ((size_t)EDIM * EDIM)

#define NHW    32      // hw segment blocks (8 n-tiles x 4 k-splits)
#define NATTN  256
#define NLOG   (VPAD / 64)   // 422
#define NGATES 96      // 32 n-tiles x 3 k-splits

// ---------------- persistent device scratch ----------------
__device__ __align__(128) float g_h[BATCH * EDIM];
__device__ __align__(128) float g_c[BATCH * EDIM];
__device__ __align__(128) float g_gatesP[5 * BATCH * GDIM];   // attth: 0..2, emb: 3..4
__device__ __align__(128) float g_hwP[4 * BATCH * EDIM];      // attn_W @ h partials
__device__ __align__(128) float g_bg[GDIM];
__device__ int   g_off[BATCH + 1];
__device__ unsigned long long g_amax[BATCH];
__device__ unsigned int g_sync[2];                            // [0]=hw arrivals, [1]=attn arrivals
__device__ __align__(128) __half g_B2[2 * PLANE_B];           // proj_W^T limbs
__device__ __align__(128) __half g_W2[2 * PLANE_W];           // [W_ih|W_hh] limbs
__device__ __align__(128) __half g_z2[2 * PLANE_Z];           // z limbs
__device__ __align__(128) __half g_h2[2 * PLANE_H];           // h limbs
__device__ __align__(128) __half g_AW2[2 * PLANE_AW];         // attn_W limbs (NOT transposed)

// ---------------- helpers ----------------
__device__ __forceinline__ uint32_t smem_u32(const void* p) {
    uint32_t a;
    asm("{ .reg .u64 t; cvta.to.shared.u64 t, %1; cvt.u32.u64 %0, t; }" : "=r"(a) : "l"(p));
    return a;
}
__device__ __forceinline__ void split2_store(float v, __half* base, size_t off, size_t plane) {
    __half h = __float2half_rn(v);
    float r = v - __half2float(h);
    base[off]         = h;
    base[off + plane] = __float2half_rn(r);
}
__device__ __forceinline__ void ldmatrix_x4(uint32_t* r, uint32_t addr) {
    asm volatile("ldmatrix.sync.aligned.m8n8.x4.shared.b16 {%0,%1,%2,%3}, [%4];"
                 : "=r"(r[0]), "=r"(r[1]), "=r"(r[2]), "=r"(r[3]) : "r"(addr) : "memory");
}
__device__ __forceinline__ void mma16816(float* c, const uint32_t* a, uint32_t b0, uint32_t b1) {
    asm volatile(
        "mma.sync.aligned.m16n8k16.row.col.f32.f16.f16.f32 "
        "{%0,%1,%2,%3}, {%4,%5,%6,%7}, {%8,%9}, {%0,%1,%2,%3};"
        : "+f"(c[0]), "+f"(c[1]), "+f"(c[2]), "+f"(c[3])
        : "r"(a[0]), "r"(a[1]), "r"(a[2]), "r"(a[3]), "r"(b0), "r"(b1));
}
__device__ __forceinline__ void cp_async16(uint32_t dst, const void* src) {
    asm volatile("cp.async.cg.shared.global [%0], [%1], 16;" :: "r"(dst), "l"(src) : "memory");
}
#define CP_COMMIT() asm volatile("cp.async.commit_group;" ::: "memory")
#define CP_WAIT0()  asm volatile("cp.async.wait_group 0;" ::: "memory")
#define CP_WAIT1()  asm volatile("cp.async.wait_group 1;" ::: "memory")

__device__ __forceinline__ unsigned long long pack_key(float v, int col) {
    uint32_t u = __float_as_uint(v);
    u = (u & 0x80000000u) ? ~u : (u | 0x80000000u);
    return ((unsigned long long)u << 32) | (unsigned long long)(0x7FFFFFFFu - (uint32_t)col);
}

__device__ __forceinline__ void spin_until(volatile unsigned int* ctr, unsigned int target) {
    if (threadIdx.x == 0) {
        while (*ctr < target) __nanosleep(200);
    }
    __syncthreads();
    __threadfence();
}
__device__ __forceinline__ void signal_done(unsigned int* ctr) {
    __syncthreads();
    __threadfence();
    if (threadIdx.x == 0) atomicAdd(ctr, 1u);
}

// ---------------- init: offsets prefix sum + initial tokens + sync reset ----------------
__global__ void init_meta_kernel(const int* __restrict__ counts,
                                 const int* __restrict__ target_labels) {
    __shared__ int s[BATCH];
    int t = threadIdx.x;
    s[t] = counts[t];
    __syncthreads();
    for (int d = 1; d < BATCH; d <<= 1) {
        int v = (t >= d) ? s[t - d] : 0;
        __syncthreads();
        s[t] += v;
        __syncthreads();
    }
    g_off[t] = s[t] - counts[t];
    if (t == 0) {
        g_off[BATCH] = s[BATCH - 1];
        g_sync[0] = 0u;
        g_sync[1] = 0u;
    }
    g_amax[t] = (unsigned long long)(0x7FFFFFFFu - (uint32_t)target_labels[t]);
}

// ---------------- prep kernels ----------------
__global__ void build_wg2_kernel(const float* __restrict__ W_ih,
                                 const float* __restrict__ W_hh,
                                 const float* __restrict__ b_ih,
                                 const float* __restrict__ b_hh) {
    int i = blockIdx.x * blockDim.x + threadIdx.x;
    if (i < GDIM * KZ) {
        int n = i / KZ, k = i % KZ;
        float v = (k < 1024) ? W_ih[(size_t)n * 1024 + k]
                             : W_hh[(size_t)n * 512 + (k - 1024)];
        split2_store(v, g_W2, (size_t)n * KZ + k, PLANE_W);
    }
    if (i < GDIM) g_bg[i] = b_ih[i] + b_hh[i];
}

__global__ void prepB2_kernel(const float* __restrict__ W) {
    __shared__ float tile[32][33];
    int n0 = blockIdx.x * 32, k0 = blockIdx.y * 32;
    int tx = threadIdx.x, ty = threadIdx.y;
#pragma unroll
    for (int i = 0; i < 4; i++) {
        int k = k0 + ty + i * 8, n = n0 + tx;
        tile[ty + i * 8][tx] = (n < VDIM) ? W[(size_t)k * VDIM + n] : 0.f;
    }
    __syncthreads();
#pragma unroll
    for (int i = 0; i < 4; i++)
        split2_store(tile[tx][ty + i * 8], g_B2,
                     (size_t)(n0 + ty + i * 8) * EDIM + k0 + tx, PLANE_B);
}

// attn_W limbs, elementwise (no transpose: B[n=e][k=d] = attn_W[e][d])
__global__ void prepAW2_kernel(const float* __restrict__ W) {
    int i = blockIdx.x * blockDim.x + threadIdx.x;
    if (i < EDIM * EDIM) split2_store(W[i], g_AW2, (size_t)i, PLANE_AW);
}

__global__ void init_h_kernel(const float* __restrict__ enc,
                              const int* __restrict__ counts) {
    int b = blockIdx.x, t = threadIdx.x;
    int cnt = counts[b], off = g_off[b];
    float2 acc = make_float2(0.f, 0.f);
    for (int c = 0; c < cnt; c++) {
        float2 v = *(const float2*)(enc + (size_t)(off + c) * EDIM + 2 * t);
        acc.x += v.x; acc.y += v.y;
    }
    float inv = 1.f / (float)cnt;
    float h0 = acc.x * inv, h1 = acc.y * inv;
    int i0 = b * EDIM + 2 * t, i1 = i0 + 1;
    g_h[i0] = h0;  g_c[i0] = h0;
    g_h[i1] = h1;  g_c[i1] = h1;
    split2_store(h0, g_h2, (size_t)i0, PLANE_H);
    split2_store(h1, g_h2, (size_t)i1, PLANE_H);
    size_t zr = (size_t)b * KZ + 1024;
    split2_store(h0, g_z2, zr + 2 * t,     PLANE_Z);
    split2_store(h1, g_z2, zr + 2 * t + 1, PLANE_Z);
}

__global__ void zero_kernel(float4* __restrict__ p, int n4) {
    for (int i = blockIdx.x * blockDim.x + threadIdx.x; i < n4; i += gridDim.x * blockDim.x)
        p[i] = make_float4(0.f, 0.f, 0.f, 0.f);
}

// ================= generic fused-limb HMMA GEMM body =================
// C[256, N] = A_h@B_h^T + A_h@B_m^T + A_m@B_h^T over Kloop columns.
// F = 2*KC fused chunks; this instance handles f = z, z+zs, ...
#define ASTAGE (256 * 128)
#define BSTAGE (64 * 128)
#define STAGE_BYTES (ASTAGE + 2 * BSTAGE)
#define SMEM_HMMA (2 * STAGE_BYTES + 128)

__device__ __forceinline__ void gemm_body(
    const __half* __restrict__ Ab, const __half* __restrict__ Bb,
    int lda, int ldb, size_t planeA, size_t planeB, int Kloop,
    const float* __restrict__ bias, float* __restrict__ out,
    int ldo, int Nvalid, unsigned long long* amax,
    int n0, int z, int zs, char* dyn_raw) {

    char* sbase = (char*)(((uintptr_t)dyn_raw + 127) & ~(uintptr_t)127);
    uint32_t sb = smem_u32(sbase);

    int tid = threadIdx.x, lane = tid & 31, warp = tid >> 5;
    int warpM = warp >> 1, warpN = warp & 1;

    const int KC = Kloop >> 6;
    const int F  = 2 * KC;
    const int NCb = (F - z + zs - 1) / zs;

    int rAl[4], rBl[2];
#pragma unroll
    for (int mt = 0; mt < 4; mt++)
        rAl[mt] = warpM * 64 + mt * 16 + (lane & 7) + ((lane >> 3) & 1) * 8;
#pragma unroll
    for (int nt = 0; nt < 2; nt++)
        rBl[nt] = warpN * 32 + nt * 16 + (lane & 7) + (lane >> 4) * 8;
    int clA = lane >> 4;
    int clB = (lane >> 3) & 1;

    int liA_r[8], liA_c[8], liB_r[2], liB_c[2];
#pragma unroll
    for (int i = 0; i < 8; i++) { int li = i * 256 + tid; liA_r[i] = li >> 3; liA_c[i] = li & 7; }
#pragma unroll
    for (int i = 0; i < 2; i++) { int li = i * 256 + tid; liB_r[i] = li >> 3; liB_c[i] = li & 7; }

    auto issue_chunk = [&](int f, int stg) {
        int aL = (f < KC) ? 0 : 1;
        int kb = ((f < KC) ? f : f - KC) << 6;
        const __half* Ap = Ab + (size_t)aL * planeA + kb;
        uint32_t dA  = sb + stg * STAGE_BYTES;
        uint32_t dBh = dA + ASTAGE;
        uint32_t dBm = dBh + BSTAGE;
#pragma unroll
        for (int i = 0; i < 8; i++) {
            int r = liA_r[i], c = liA_c[i];
            cp_async16(dA + r * 128 + ((c ^ (r & 7)) << 4),
                       Ap + (size_t)r * lda + c * 8);
        }
        const __half* Bph = Bb + kb;
#pragma unroll
        for (int i = 0; i < 2; i++) {
            int r = liB_r[i], c = liB_c[i];
            cp_async16(dBh + r * 128 + ((c ^ (r & 7)) << 4),
                       Bph + (size_t)(n0 + r) * ldb + c * 8);
        }
        if (f < KC) {
            const __half* Bpm = Bb + planeB + kb;
#pragma unroll
            for (int i = 0; i < 2; i++) {
                int r = liB_r[i], c = liB_c[i];
                cp_async16(dBm + r * 128 + ((c ^ (r & 7)) << 4),
                           Bpm + (size_t)(n0 + r) * ldb + c * 8);
            }
        }
        CP_COMMIT();
    };

    float acc[4][4][4];
#pragma unroll
    for (int a = 0; a < 4; a++)
#pragma unroll
        for (int b = 0; b < 4; b++)
#pragma unroll
            for (int c = 0; c < 4; c++) acc[a][b][c] = 0.f;

    issue_chunk(z, 0);
    if (NCb > 1) issue_chunk(z + zs, 1);

    for (int i = 0; i < NCb; i++) {
        int f = z + i * zs;
        if (i + 1 < NCb) { CP_WAIT1(); } else { CP_WAIT0(); }
        __syncthreads();

        int stg = i & 1;
        uint32_t sAb  = sb + stg * STAGE_BYTES;
        uint32_t sBhb = sAb + ASTAGE;
        uint32_t sBmb = sBhb + BSTAGE;
        bool two = (f < KC);
#pragma unroll
        for (int h = 0; h < 4; h++) {
            uint32_t af[4][4], bfh[2][4];
#pragma unroll
            for (int mt = 0; mt < 4; mt++) {
                int r = rAl[mt];
                int c = (h * 2 + clA) ^ (r & 7);
                ldmatrix_x4(af[mt], sAb + r * 128 + (c << 4));
            }
#pragma unroll
            for (int nt = 0; nt < 2; nt++) {
                int r = rBl[nt];
                int c = (h * 2 + clB) ^ (r & 7);
                ldmatrix_x4(bfh[nt], sBhb + r * 128 + (c << 4));
            }
#pragma unroll
            for (int mt = 0; mt < 4; mt++)
#pragma unroll
                for (int nt = 0; nt < 2; nt++)
#pragma unroll
                    for (int j = 0; j < 2; j++)
                        mma16816(acc[mt][nt * 2 + j], af[mt], bfh[nt][2 * j], bfh[nt][2 * j + 1]);
            if (two) {
                uint32_t bfm[2][4];
#pragma unroll
                for (int nt = 0; nt < 2; nt++) {
                    int r = rBl[nt];
                    int c = (h * 2 + clB) ^ (r & 7);
                    ldmatrix_x4(bfm[nt], sBmb + r * 128 + (c << 4));
                }
#pragma unroll
                for (int mt = 0; mt < 4; mt++)
#pragma unroll
                    for (int nt = 0; nt < 2; nt++)
#pragma unroll
                        for (int j = 0; j < 2; j++)
                            mma16816(acc[mt][nt * 2 + j], af[mt], bfm[nt][2 * j], bfm[nt][2 * j + 1]);
            }
        }
        __syncthreads();
        if (i + 2 < NCb) issue_chunk(z + (i + 2) * zs, stg);
    }

    // ---- epilogue: bias + store (+ fused argmax) ----
#pragma unroll
    for (int mt = 0; mt < 4; mt++) {
        int row0 = warpM * 64 + mt * 16 + (lane >> 2);
        unsigned long long k0 = 0ull, k1 = 0ull;
#pragma unroll
        for (int n8 = 0; n8 < 4; n8++) {
            int col = n0 + warpN * 32 + n8 * 8 + (lane & 3) * 2;
            if (col < Nvalid) {
                float bx = bias ? bias[col] : 0.f;
                float by = bias ? bias[col + 1] : 0.f;
                float v0 = acc[mt][n8][0] + bx, v1 = acc[mt][n8][1] + by;
                float v2 = acc[mt][n8][2] + bx, v3 = acc[mt][n8][3] + by;
                *(float2*)(out + (size_t)row0 * ldo + col)       = make_float2(v0, v1);
                *(float2*)(out + (size_t)(row0 + 8) * ldo + col) = make_float2(v2, v3);
                if (amax) {
                    unsigned long long ka = pack_key(v0, col), kb2 = pack_key(v1, col + 1);
                    k0 = k0 > ka ? k0 : ka; k0 = k0 > kb2 ? k0 : kb2;
                    ka = pack_key(v2, col); kb2 = pack_key(v3, col + 1);
                    k1 = k1 > ka ? k1 : ka; k1 = k1 > kb2 ? k1 : kb2;
                }
            }
        }
        if (amax) {
#pragma unroll
            for (int o = 1; o <= 2; o <<= 1) {
                unsigned long long t0 = __shfl_xor_sync(0xFFFFFFFFu, k0, o);
                unsigned long long t1 = __shfl_xor_sync(0xFFFFFFFFu, k1, o);
                k0 = k0 > t0 ? k0 : t0;
                k1 = k1 > t1 ? k1 : t1;
            }
            if ((lane & 3) == 0) {
                if (k0) atomicMax(&amax[row0], k0);
                if (k1) atomicMax(&amax[row0 + 8], k1);
            }
        }
    }
}

// ---------------- attn block body: scores via hw, softmax, attended ----------------
__device__ void attn_block_body(const float* __restrict__ enc,
                                const int* __restrict__ counts,
                                int b, unsigned int hwTarget, char* dyn) {
    int t = threadIdx.x;
    int lane = t & 31, w = t >> 5;     // 8 warps
    float* hws = (float*)dyn;          // 512
    float* sc  = hws + EDIM;           // CMAX
    float* red = sc + CMAX;            // 256

    spin_until(&g_sync[0], hwTarget);

    // sum 4 hw partial planes
    {
        float s0 = g_hwP[0 * BATCH * EDIM + b * EDIM + t]
                 + g_hwP[1 * BATCH * EDIM + b * EDIM + t]
                 + g_hwP[2 * BATCH * EDIM + b * EDIM + t]
                 + g_hwP[3 * BATCH * EDIM + b * EDIM + t];
        float s1 = g_hwP[0 * BATCH * EDIM + b * EDIM + t + 256]
                 + g_hwP[1 * BATCH * EDIM + b * EDIM + t + 256]
                 + g_hwP[2 * BATCH * EDIM + b * EDIM + t + 256]
                 + g_hwP[3 * BATCH * EDIM + b * EDIM + t + 256];
        hws[t] = s0;
        hws[t + 256] = s1;
    }
    __syncthreads();

    int cnt = counts[b], off = g_off[b];

    for (int c = w; c < cnt; c += 8) {
        const float* row = enc + (size_t)(off + c) * EDIM;
        float s = 0.f;
#pragma unroll
        for (int j = 0; j < EDIM; j += 128) {
            float4 v = *(const float4*)(row + j + lane * 4);
            s += v.x * hws[j + lane * 4]     + v.y * hws[j + lane * 4 + 1]
               + v.z * hws[j + lane * 4 + 2] + v.w * hws[j + lane * 4 + 3];
        }
#pragma unroll
        for (int o = 16; o; o >>= 1) s += __shfl_xor_sync(0xFFFFFFFFu, s, o);
        if (lane == 0) sc[c] = s;
    }
    __syncthreads();

    float m = -3.4e38f;
    for (int c = t; c < cnt; c += 256) m = fmaxf(m, sc[c]);
    red[t] = m;
    __syncthreads();
    for (int d = 128; d; d >>= 1) {
        if (t < d) red[t] = fmaxf(red[t], red[t + d]);
        __syncthreads();
    }
    float mx = red[0];
    __syncthreads();

    float s = 0.f;
    for (int c = t; c < cnt; c += 256) {
        float e = expf(sc[c] - mx);
        sc[c] = e;
        s += e;
    }
    red[t] = s;
    __syncthreads();
    for (int d = 128; d; d >>= 1) {
        if (t < d) red[t] += red[t + d];
        __syncthreads();
    }
    float inv = 1.f / red[0];

    float2 a0 = make_float2(0.f, 0.f), a1 = a0, a2 = a0, a3 = a0;
    const float* ebase = enc + (size_t)off * EDIM + 2 * t;
    int c = 0;
    for (; c + 4 <= cnt; c += 4) {
        float w0 = sc[c], w1 = sc[c + 1], w2 = sc[c + 2], w3 = sc[c + 3];
        float2 v0 = *(const float2*)(ebase + (size_t)c * EDIM);
        float2 v1 = *(const float2*)(ebase + (size_t)(c + 1) * EDIM);
        float2 v2 = *(const float2*)(ebase + (size_t)(c + 2) * EDIM);
        float2 v3 = *(const float2*)(ebase + (size_t)(c + 3) * EDIM);
        a0.x += w0 * v0.x; a0.y += w0 * v0.y;
        a1.x += w1 * v1.x; a1.y += w1 * v1.y;
        a2.x += w2 * v2.x; a2.y += w2 * v2.y;
        a3.x += w3 * v3.x; a3.y += w3 * v3.y;
    }
    for (; c < cnt; c++) {
        float w0 = sc[c];
        float2 v0 = *(const float2*)(ebase + (size_t)c * EDIM);
        a0.x += w0 * v0.x; a0.y += w0 * v0.y;
    }
    float ax = ((a0.x + a1.x) + (a2.x + a3.x)) * inv;
    float ay = ((a0.y + a1.y) + (a2.y + a3.y)) * inv;

    size_t zr = (size_t)b * KZ;
    split2_store(ax, g_z2, zr + 512 + 2 * t,     PLANE_Z);
    split2_store(ay, g_z2, zr + 512 + 2 * t + 1, PLANE_Z);

    signal_done(&g_sync[1]);
}

// ================= mega kernel: [hw][attn][logits][gates_attth] =================
__global__ void __launch_bounds__(256, 2) mega_kernel(
    float* __restrict__ logits_out, const float* __restrict__ proj_b,
    unsigned long long* amax, int nHw, int nAttn, int nLog, int nGates,
    unsigned int step, const float* __restrict__ enc, const int* __restrict__ counts) {

    extern __shared__ char dyn_raw[];
    int bx = blockIdx.x;

    if (bx < nHw) {
        // hw = attn_W @ h : M=256, N=512, K=512 ; 8 n-tiles x 4 k-splits
        int z = bx >> 3, n0 = (bx & 7) * 64;
        gemm_body(g_h2, g_AW2, EDIM, EDIM, PLANE_H, PLANE_AW, EDIM,
                  nullptr, g_hwP + (size_t)z * BATCH * EDIM, EDIM, EDIM,
                  nullptr, n0, z, 4, dyn_raw);
        signal_done(&g_sync[0]);
        return;
    }
    bx -= nHw;
    if (bx < nAttn) {
        attn_block_body(enc, counts, bx, step * NHW, dyn_raw);
        return;
    }
    bx -= nAttn;
    if (bx < nLog) {
        gemm_body(g_h2, g_B2, EDIM, EDIM, PLANE_H, PLANE_B, EDIM,
                  proj_b, logits_out, VDIM, VDIM, amax, bx * 64, 0, 1, dyn_raw);
        return;
    }
    bx -= nLog;
    if (bx < nGates) {
        // gates over K in [512,1536): needs attended (attn) + h (lstm of prev step)
        int z = bx >> 5, n0 = (bx & 31) * 64;
        spin_until(&g_sync[1], step * NATTN);
        gemm_body(g_z2 + 512, g_W2 + 512, KZ, KZ, PLANE_Z, PLANE_W, 1024,
                  nullptr, g_gatesP + (size_t)z * BATCH * GDIM, GDIM, GDIM,
                  nullptr, n0, z, 3, dyn_raw);
    }
}

// ---------------- gates over K in [0,512) (emb slot), planes 3..4 ----------------
__global__ void __launch_bounds__(256, 2) gates_emb_kernel() {
    extern __shared__ char dyn_raw[];
    gemm_body(g_z2, g_W2, KZ, KZ, PLANE_Z, PLANE_W, EDIM,
              nullptr, g_gatesP + (size_t)(3 + blockIdx.z) * BATCH * GDIM,
              GDIM, GDIM, nullptr, blockIdx.x * 64, blockIdx.z, 2, dyn_raw);
}

// ---------------- emb lookup -> z slot [0,512) limbs ----------------
__global__ void emb_z_kernel(const float* __restrict__ emb) {
    int b = blockIdx.x, t = threadIdx.x;
    int tok = 0x7FFFFFFF - (int)(uint32_t)(g_amax[b] & 0xFFFFFFFFull);
    size_t zr = (size_t)b * KZ;
    split2_store(emb[(size_t)tok * EDIM + t],       g_z2, zr + t,       PLANE_Z);
    split2_store(emb[(size_t)tok * EDIM + t + 256], g_z2, zr + t + 256, PLANE_Z);
}

// ---------------- LSTM: sum 5 partial planes + bias; update h/c + limbs; reset amax ----------------
__global__ void lstm_kernel() {
    int idx = blockIdx.x * blockDim.x + threadIdx.x;
    if (idx < BATCH) g_amax[idx] = 0ull;
    int b = idx >> 9, e = idx & 511;
    const float* g0 = g_gatesP + (size_t)b * GDIM;
    const size_t P = (size_t)BATCH * GDIM;
    float gi = g_bg[e],        gf = g_bg[512 + e];
    float gg = g_bg[1024 + e], go = g_bg[1536 + e];
#pragma unroll
    for (int p = 0; p < 5; p++) {
        gi += g0[p * P + e];
        gf += g0[p * P + 512 + e];
        gg += g0[p * P + 1024 + e];
        go += g0[p * P + 1536 + e];
    }
    float si = 1.f / (1.f + expf(-gi));
    float sf = 1.f / (1.f + expf(-gf));
    float so = 1.f / (1.f + expf(-go));
    float cn = sf * g_c[idx] + si * tanhf(gg);
    float hn = so * tanhf(cn);
    g_c[idx] = cn;
    g_h[idx] = hn;
    split2_store(hn, g_h2, (size_t)idx, PLANE_H);
    split2_store(hn, g_z2, (size_t)b * KZ + 1024 + e, PLANE_Z);
}

// ---------------- launch ----------------
extern "C" void kernel_launch(void* const* d_in, const int* in_sizes, int n_in,
                              void* d_out, int out_size) {
    const float* enc    = (const float*)d_in[0];
    const int*   tl     = (const int*)d_in[1];
    const int*   counts = (const int*)d_in[2];
    const float* emb    = (const float*)d_in[3];
    const float* attn_W = (const float*)d_in[4];
    // d_in[5] = attn_b : drops out (softmax shift invariance; masked lanes exact 0)
    const float* W_ih   = (const float*)d_in[6];
    const float* W_hh   = (const float*)d_in[7];
    const float* b_ih   = (const float*)d_in[8];
    const float* b_hh   = (const float*)d_in[9];
    const float* proj_W = (const float*)d_in[10];
    const float* proj_b = (const float*)d_in[11];
    float* out = (float*)d_out;

    unsigned long long* pAmax;
    cudaGetSymbolAddress((void**)&pAmax, g_amax);

    cudaFuncSetAttribute(mega_kernel,
                         cudaFuncAttributeMaxDynamicSharedMemorySize, SMEM_HMMA);
    cudaFuncSetAttribute(gates_emb_kernel,
                         cudaFuncAttributeMaxDynamicSharedMemorySize, SMEM_HMMA);

    zero_kernel<<<2048, 256>>>((float4*)out, BATCH * VDIM / 4);
    init_meta_kernel<<<1, BATCH>>>(counts, tl);
    build_wg2_kernel<<<(GDIM * KZ + 255) / 256, 256>>>(W_ih, W_hh, b_ih, b_hh);
    {
        dim3 grid(VPAD / 32, EDIM / 32);
        prepB2_kernel<<<grid, dim3(32, 8)>>>(proj_W);
    }
    prepAW2_kernel<<<(EDIM * EDIM + 255) / 256, 256>>>(attn_W);
    init_h_kernel<<<BATCH, 256>>>(enc, counts);

    dim3 grid_ge(32, 1, 2);

    // per step t: mega[hw(t), attn(t), logits(t-1), gates_attth(t)]
    //             -> emb_z(t) -> gates_emb(t) -> lstm(t)
    for (unsigned int t = 1; t < LSTEPS; t++) {
        int nlog = (t >= 2) ? NLOG : 0;
        float* logits = out + (size_t)(t - 1) * BATCH * VDIM;
        mega_kernel<<<NHW + NATTN + nlog + NGATES, 256, SMEM_HMMA>>>(
            logits, proj_b, (t >= 2) ? pAmax : nullptr,
            NHW, NATTN, nlog, NGATES, t, enc, counts);
        emb_z_kernel<<<BATCH, 256>>>(emb);
        gates_emb_kernel<<<grid_ge, 256, SMEM_HMMA>>>();
        lstm_kernel<<<BATCH * EDIM / 256, 256>>>();
    }
    {   // final logits (step 15)
        float* logits = out + (size_t)(LSTEPS - 1) * BATCH * VDIM;
        mega_kernel<<<NLOG, 256, SMEM_HMMA>>>(
            logits, proj_b, nullptr, 0, 0, NLOG, 0, 0, enc, counts);
    }
}